// round 3
// baseline (speedup 1.0000x reference)
#include <cuda_runtime.h>
#include <math.h>

// Problem constants
#define BB   4
#define SS   2048
#define DD   768
#define HH   12
#define HDD  64
#define FF   3072
#define ROWS (BB*SS)   // 8192
#define NC   2304      // 3*DD packed qkv cols

// ---------------- scratch (device globals; no runtime allocation) ----------
__device__ float g_h  [ROWS*DD];   // LN out (reused for LN1 and LN2)
__device__ float g_qkv[ROWS*NC];   // packed q|k|v, layout [row][part*768 + h*64 + e]
__device__ float g_o  [ROWS*DD];   // attention output, [row][h*64+e]
__device__ float g_a  [ROWS*DD];   // after Wo
__device__ float g_f  [ROWS*FF];   // FFN intermediate
__device__ float g_Wp [DD*NC];     // packed QKV weights [d][part*768 + h*64 + e]
__device__ float g_bp [NC];        // packed QKV bias

// ---------------- weight packing --------------------------------------------
__global__ void pack_kernel(const float* __restrict__ Wq, const float* __restrict__ Wk,
                            const float* __restrict__ Wv, const float* __restrict__ bq,
                            const float* __restrict__ bk, const float* __restrict__ bv)
{
    int idx = blockIdx.x * 256 + threadIdx.x;          // over DD*NC
    if (idx >= DD * NC) return;
    int d  = idx / NC;
    int j  = idx - d * NC;
    int part = j / DD;
    int jj = j - part * DD;        // h*64 + e
    int h = jj >> 6, e = jj & 63;
    const float* W = (part == 0) ? Wq : (part == 1) ? Wk : Wv;
    g_Wp[idx] = W[(h * DD + d) * HDD + e];
    if (d == 0) {
        const float* bb = (part == 0) ? bq : (part == 1) ? bk : bv;
        g_bp[j] = bb[jj];
    }
}

// ---------------- layer norm -------------------------------------------------
__global__ void ln_kernel(const float* __restrict__ x, const float* __restrict__ g,
                          const float* __restrict__ b, float* __restrict__ y)
{
    int row = blockIdx.x;
    int tid = threadIdx.x;                 // 256 threads, 768 cols
    const float* xr = x + (size_t)row * DD;
    float v0 = xr[tid], v1 = xr[tid + 256], v2 = xr[tid + 512];
    float s  = v0 + v1 + v2;
    float ss = v0 * v0 + v1 * v1 + v2 * v2;
    #pragma unroll
    for (int o = 16; o >= 1; o >>= 1) {
        s  += __shfl_xor_sync(0xffffffffu, s,  o);
        ss += __shfl_xor_sync(0xffffffffu, ss, o);
    }
    __shared__ float rs[8], rss[8];
    int w = tid >> 5, l = tid & 31;
    if (l == 0) { rs[w] = s; rss[w] = ss; }
    __syncthreads();
    float S = 0.f, S2 = 0.f;
    #pragma unroll
    for (int i = 0; i < 8; i++) { S += rs[i]; S2 += rss[i]; }
    float mu  = S  * (1.0f / DD);
    float var = S2 * (1.0f / DD) - mu * mu;
    float inv = rsqrtf(var + 1e-5f);
    float* yr = y + (size_t)row * DD;
    yr[tid      ] = (v0 - mu) * inv * g[tid      ] + b[tid      ];
    yr[tid + 256] = (v1 - mu) * inv * g[tid + 256] + b[tid + 256];
    yr[tid + 512] = (v2 - mu) * inv * g[tid + 512] + b[tid + 512];
}

// ---------------- SGEMM 128x128x8, 256 threads, 8x8 microtile ---------------
// C[M,N] = A[M,K] @ B[K,N] + bias[N], optional exact-erf GELU.
__device__ __forceinline__ float gelu_exact(float x) {
    return 0.5f * x * (1.0f + erff(x * 0.70710678118654752f));
}

template<int ACT>
__global__ __launch_bounds__(256)
void sgemm(const float* __restrict__ A, const float* __restrict__ Bm,
           const float* __restrict__ bias, float* __restrict__ C,
           int M, int N, int K)
{
    __shared__ float As[8][128];   // transposed A tile
    __shared__ float Bs[8][128];
    int tid = threadIdx.x;
    int tx = tid & 15, ty = tid >> 4;

    const float* Ab = A + (size_t)blockIdx.y * 128 * K;
    const float* Bb = Bm + blockIdx.x * 128;

    int aRow = tid >> 1, aCol = (tid & 1) << 2;      // A: 128 rows x 8 cols
    int bRow = tid >> 5, bCol = (tid & 31) << 2;     // B: 8 rows x 128 cols

    float acc[8][8];
    #pragma unroll
    for (int i = 0; i < 8; i++)
        #pragma unroll
        for (int j = 0; j < 8; j++) acc[i][j] = 0.f;

    for (int k0 = 0; k0 < K; k0 += 8) {
        float4 av = *(const float4*)(Ab + (size_t)aRow * K + k0 + aCol);
        As[aCol + 0][aRow] = av.x;
        As[aCol + 1][aRow] = av.y;
        As[aCol + 2][aRow] = av.z;
        As[aCol + 3][aRow] = av.w;
        *(float4*)(&Bs[bRow][bCol]) = *(const float4*)(Bb + (size_t)(k0 + bRow) * N + bCol);
        __syncthreads();
        #pragma unroll
        for (int k = 0; k < 8; k++) {
            float ra[8], rb[8];
            *(float4*)&ra[0] = *(const float4*)&As[k][ty << 2];
            *(float4*)&ra[4] = *(const float4*)&As[k][64 + (ty << 2)];
            *(float4*)&rb[0] = *(const float4*)&Bs[k][tx << 2];
            *(float4*)&rb[4] = *(const float4*)&Bs[k][64 + (tx << 2)];
            #pragma unroll
            for (int i = 0; i < 8; i++)
                #pragma unroll
                for (int j = 0; j < 8; j++)
                    acc[i][j] = fmaf(ra[i], rb[j], acc[i][j]);
        }
        __syncthreads();
    }

    int crow0 = blockIdx.y * 128;
    int ccol0 = blockIdx.x * 128;
    #pragma unroll
    for (int i = 0; i < 8; i++) {
        int r = crow0 + ((i < 4) ? ((ty << 2) + i) : (64 + (ty << 2) + i - 4));
        #pragma unroll
        for (int jh = 0; jh < 2; jh++) {
            int c = ccol0 + jh * 64 + (tx << 2);
            float4 v;
            v.x = acc[i][jh * 4 + 0] + bias[c + 0];
            v.y = acc[i][jh * 4 + 1] + bias[c + 1];
            v.z = acc[i][jh * 4 + 2] + bias[c + 2];
            v.w = acc[i][jh * 4 + 3] + bias[c + 3];
            if (ACT == 1) {
                v.x = gelu_exact(v.x); v.y = gelu_exact(v.y);
                v.z = gelu_exact(v.z); v.w = gelu_exact(v.w);
            }
            *(float4*)(C + (size_t)r * N + c) = v;
        }
    }
}

// ---------------- flash attention (fp32, 64x64 tiles) -----------------------
// XOR swizzle for transposed tiles: element (d, r) of a 64x64 tile stored at
// d*64 + (((r>>2) ^ swz(d)) << 2) + (r&3). Keeps float4 compute loads
// conflict-free and transpose stores <=2-way conflicted.
__device__ __forceinline__ int swz4(int d)           { return (d + (d >> 2)) & 15; }
__device__ __forceinline__ int tr_idx(int d, int r)  { return d * 64 + ((((r >> 2) ^ swz4(d)) & 15) << 2) + (r & 3); }

__global__ __launch_bounds__(256)
void attn_kernel(const float* __restrict__ qkv, float* __restrict__ out)
{
    __shared__ float QsT[64 * 64];   // transposed+swizzled, pre-scaled by 1/8
    __shared__ float KsT[64 * 64];   // transposed+swizzled; reused as P^T
    __shared__ float Vs [64 * 64];   // natural [key][dim]

    int bh = blockIdx.y;
    int b = bh / HH, h = bh - b * HH;
    int q0 = blockIdx.x * 64;
    int tid = threadIdx.x;
    int tx = tid & 15, ty = tid >> 4;

    const float* qb = qkv + (size_t)b * SS * NC + h * 64;
    const float* kb = qb + 768;
    const float* vb = qb + 1536;

    // load Q tile (transposed, swizzled, scaled)
    for (int idx = tid; idx < 1024; idx += 256) {
        int r = idx >> 4;
        int dbase = (idx & 15) << 2;
        float4 v = *(const float4*)(qb + (size_t)(q0 + r) * NC + dbase);
        QsT[tr_idx(dbase + 0, r)] = v.x * 0.125f;
        QsT[tr_idx(dbase + 1, r)] = v.y * 0.125f;
        QsT[tr_idx(dbase + 2, r)] = v.z * 0.125f;
        QsT[tr_idx(dbase + 3, r)] = v.w * 0.125f;
    }

    float o[4][4];
    float m[4], lsum[4];
    #pragma unroll
    for (int i = 0; i < 4; i++) {
        m[i] = -1e30f; lsum[i] = 0.f;
        #pragma unroll
        for (int j = 0; j < 4; j++) o[i][j] = 0.f;
    }

    for (int kt = 0; kt < SS / 64; kt++) {
        __syncthreads();   // protect previous PV reads (and first-iter Q store)
        int k0 = kt * 64;
        for (int idx = tid; idx < 1024; idx += 256) {
            int r = idx >> 4;
            int dbase = (idx & 15) << 2;
            float4 kv = *(const float4*)(kb + (size_t)(k0 + r) * NC + dbase);
            KsT[tr_idx(dbase + 0, r)] = kv.x;
            KsT[tr_idx(dbase + 1, r)] = kv.y;
            KsT[tr_idx(dbase + 2, r)] = kv.z;
            KsT[tr_idx(dbase + 3, r)] = kv.w;
            float4 vv = *(const float4*)(vb + (size_t)(k0 + r) * NC + dbase);
            *(float4*)&Vs[r * 64 + dbase] = vv;
        }
        __syncthreads();

        // S = Q K^T  (rows: ty*4+i, keys: tx*4+j)
        float s[4][4];
        #pragma unroll
        for (int i = 0; i < 4; i++)
            #pragma unroll
            for (int j = 0; j < 4; j++) s[i][j] = 0.f;
        #pragma unroll
        for (int d = 0; d < 64; d++) {
            int c = swz4(d);
            float4 ra = *(const float4*)&QsT[d * 64 + ((ty ^ c) << 2)];
            float4 rb = *(const float4*)&KsT[d * 64 + ((tx ^ c) << 2)];
            float qa[4] = {ra.x, ra.y, ra.z, ra.w};
            float ka[4] = {rb.x, rb.y, rb.z, rb.w};
            #pragma unroll
            for (int i = 0; i < 4; i++)
                #pragma unroll
                for (int j = 0; j < 4; j++)
                    s[i][j] = fmaf(qa[i], ka[j], s[i][j]);
        }

        // row max across 16 tx-lanes
        float tmax[4];
        #pragma unroll
        for (int i = 0; i < 4; i++) {
            float t = fmaxf(fmaxf(s[i][0], s[i][1]), fmaxf(s[i][2], s[i][3]));
            #pragma unroll
            for (int off = 8; off >= 1; off >>= 1)
                t = fmaxf(t, __shfl_xor_sync(0xffffffffu, t, off));
            tmax[i] = t;
        }
        float alpha[4];
        #pragma unroll
        for (int i = 0; i < 4; i++) {
            float mn = fmaxf(m[i], tmax[i]);
            alpha[i] = __expf(m[i] - mn);
            m[i] = mn;
        }
        float rsum[4];
        #pragma unroll
        for (int i = 0; i < 4; i++) {
            float acc = 0.f;
            #pragma unroll
            for (int j = 0; j < 4; j++) {
                float p = __expf(s[i][j] - m[i]);
                s[i][j] = p;
                acc += p;
            }
            #pragma unroll
            for (int off = 8; off >= 1; off >>= 1)
                acc += __shfl_xor_sync(0xffffffffu, acc, off);
            rsum[i] = acc;
        }
        #pragma unroll
        for (int i = 0; i < 4; i++) {
            lsum[i] = lsum[i] * alpha[i] + rsum[i];
            #pragma unroll
            for (int j = 0; j < 4; j++) o[i][j] *= alpha[i];
        }

        __syncthreads();   // done reading KsT as K
        // store P transposed into KsT region: logical (key, row)
        #pragma unroll
        for (int i = 0; i < 4; i++)
            #pragma unroll
            for (int j = 0; j < 4; j++)
                KsT[tr_idx((tx << 2) + j, (ty << 2) + i)] = s[i][j];
        __syncthreads();

        // O += P V  (rows ty*4+i, dims tx*4+j; reduce over keys)
        #pragma unroll
        for (int k = 0; k < 64; k++) {
            int c = swz4(k);
            float4 pa = *(const float4*)&KsT[k * 64 + ((ty ^ c) << 2)];
            float4 vv = *(const float4*)&Vs[k * 64 + (tx << 2)];
            float pv[4] = {pa.x, pa.y, pa.z, pa.w};
            float vr[4] = {vv.x, vv.y, vv.z, vv.w};
            #pragma unroll
            for (int i = 0; i < 4; i++)
                #pragma unroll
                for (int j = 0; j < 4; j++)
                    o[i][j] = fmaf(pv[i], vr[j], o[i][j]);
        }
    }

    // write O / l  to [row][h*64+dim]
    #pragma unroll
    for (int i = 0; i < 4; i++) {
        int row = q0 + (ty << 2) + i;
        float inv = 1.0f / lsum[i];
        float4 v;
        v.x = o[i][0] * inv; v.y = o[i][1] * inv;
        v.z = o[i][2] * inv; v.w = o[i][3] * inv;
        *(float4*)(out + (size_t)(b * SS + row) * DD + h * 64 + (tx << 2)) = v;
    }
}

// ---------------- launch -----------------------------------------------------
extern "C" void kernel_launch(void* const* d_in, const int* in_sizes, int n_in,
                              void* d_out, int out_size)
{
    const float* x   = (const float*)d_in[0];
    const float* Wq  = (const float*)d_in[1];
    const float* bq  = (const float*)d_in[2];
    const float* Wk  = (const float*)d_in[3];
    const float* bk  = (const float*)d_in[4];
    const float* Wv  = (const float*)d_in[5];
    const float* bv  = (const float*)d_in[6];
    const float* Wo  = (const float*)d_in[7];
    const float* bo  = (const float*)d_in[8];
    const float* W1  = (const float*)d_in[9];
    const float* b1  = (const float*)d_in[10];
    const float* W2  = (const float*)d_in[11];
    const float* b2  = (const float*)d_in[12];
    const float* g1  = (const float*)d_in[13];
    const float* be1 = (const float*)d_in[14];
    const float* g2  = (const float*)d_in[15];
    const float* be2 = (const float*)d_in[16];
    float* out = (float*)d_out;

    void *ph, *pqkv, *po, *pa, *pf, *pWp, *pbp;
    cudaGetSymbolAddress(&ph,   g_h);
    cudaGetSymbolAddress(&pqkv, g_qkv);
    cudaGetSymbolAddress(&po,   g_o);
    cudaGetSymbolAddress(&pa,   g_a);
    cudaGetSymbolAddress(&pf,   g_f);
    cudaGetSymbolAddress(&pWp,  g_Wp);
    cudaGetSymbolAddress(&pbp,  g_bp);
    float* h   = (float*)ph;
    float* qkv = (float*)pqkv;
    float* o   = (float*)po;
    float* a   = (float*)pa;
    float* f   = (float*)pf;
    float* Wp  = (float*)pWp;
    float* bp  = (float*)pbp;

    // 1. pack QKV weights
    pack_kernel<<<(DD * NC + 255) / 256, 256>>>(Wq, Wk, Wv, bq, bk, bv);
    // 2. LN1
    ln_kernel<<<ROWS, 256>>>(x, g1, be1, h);
    // 3. QKV projection
    sgemm<0><<<dim3(NC / 128, ROWS / 128), 256>>>(h, Wp, bp, qkv, ROWS, NC, DD);
    // 4. attention
    attn_kernel<<<dim3(SS / 64, BB * HH), 256>>>(qkv, o);
    // 5. output projection
    sgemm<0><<<dim3(DD / 128, ROWS / 128), 256>>>(o, Wo, bo, a, ROWS, DD, DD);
    // 6. LN2
    ln_kernel<<<ROWS, 256>>>(a, g2, be2, h);
    // 7. FFN up + GELU
    sgemm<1><<<dim3(FF / 128, ROWS / 128), 256>>>(h, W1, b1, f, ROWS, FF, DD);
    // 8. FFN down -> output
    sgemm<0><<<dim3(DD / 128, ROWS / 128), 256>>>(f, W2, b2, out, ROWS, DD, FF);
}

// round 5
// speedup vs baseline: 1.5412x; 1.5412x over previous
#include <cuda_runtime.h>
#include <cuda_bf16.h>
#include <math.h>
#include <stdint.h>

// Problem constants
#define BB   4
#define SS   2048
#define DD   768
#define HH   12
#define HDD  64
#define FF   3072
#define ROWS (BB*SS)   // 8192
#define NC   2304      // 3*DD packed qkv cols

// ---------------- scratch (device globals; no runtime allocation) ----------
__device__ float g_qkv[ROWS*NC];                 // packed q|k|v fp32
__device__ float g_a  [ROWS*DD];                 // after Wo (fp32, LN2 input)
__device__ float g_bp [NC];                      // packed QKV bias
__device__ __align__(256) __nv_bfloat16 g_h_hi[ROWS*DD], g_h_lo[ROWS*DD];
__device__ __align__(256) __nv_bfloat16 g_o_hi[ROWS*DD], g_o_lo[ROWS*DD];
__device__ __align__(256) __nv_bfloat16 g_f_hi[ROWS*FF], g_f_lo[ROWS*FF];
__device__ __align__(256) __nv_bfloat16 g_Wqkv_hi[NC*DD], g_Wqkv_lo[NC*DD]; // [2304][768]
__device__ __align__(256) __nv_bfloat16 g_Wo_hi[DD*DD],  g_Wo_lo[DD*DD];    // [768][768]
__device__ __align__(256) __nv_bfloat16 g_W1_hi[FF*DD],  g_W1_lo[FF*DD];    // [3072][768]
__device__ __align__(256) __nv_bfloat16 g_W2_hi[DD*FF],  g_W2_lo[DD*FF];    // [768][3072]

// ================= PTX helpers (baseline ISA only: sm_80-class) =============
__device__ __forceinline__ uint32_t smem_u32(const void* p) {
    uint32_t a;
    asm("{ .reg .u64 t; cvta.to.shared.u64 t, %1; cvt.u32.u64 %0, t; }" : "=r"(a) : "l"(p));
    return a;
}
#define CP16(dst, src) asm volatile("cp.async.cg.shared.global [%0], [%1], 16;" :: "r"(dst), "l"(src))
#define CP_COMMIT()    asm volatile("cp.async.commit_group;" ::: "memory")
#define CP_WAIT(n)     asm volatile("cp.async.wait_group %0;" :: "n"(n) : "memory")

#define LDM4(r, addr) \
    asm volatile("ldmatrix.sync.aligned.m8n8.x4.shared.b16 {%0,%1,%2,%3}, [%4];" \
        : "=r"((r)[0]), "=r"((r)[1]), "=r"((r)[2]), "=r"((r)[3]) : "r"(addr))

#define MMA16816(d, a, b0v, b1v) \
    asm volatile("mma.sync.aligned.m16n8k16.row.col.f32.bf16.bf16.f32 " \
        "{%0,%1,%2,%3},{%4,%5,%6,%7},{%8,%9},{%0,%1,%2,%3};" \
        : "+f"((d)[0]), "+f"((d)[1]), "+f"((d)[2]), "+f"((d)[3]) \
        : "r"((a)[0]), "r"((a)[1]), "r"((a)[2]), "r"((a)[3]), "r"(b0v), "r"(b1v))

__device__ __forceinline__ void split_bf16(float v, __nv_bfloat16& hi, __nv_bfloat16& lo) {
    hi = __float2bfloat16(v);
    lo = __float2bfloat16(v - __bfloat162float(hi));
}
__device__ __forceinline__ float gelu_exact(float x) {
    return 0.5f * x * (1.0f + erff(x * 0.70710678118654752f));
}

// ================= weight conversion =================
__global__ void qkv_cvt(const float* __restrict__ Wq, const float* __restrict__ Wk,
                        const float* __restrict__ Wv, const float* __restrict__ bq,
                        const float* __restrict__ bk, const float* __restrict__ bv)
{
    int idx = blockIdx.x * 256 + threadIdx.x;     // over NC*DD
    if (idx >= NC * DD) return;
    int j = idx / DD;                              // out row: part*768 + h*64 + e
    int d = idx - j * DD;
    int part = j / DD;
    int jj = j - part * DD;
    int h = jj >> 6, e = jj & 63;
    const float* W = (part == 0) ? Wq : (part == 1) ? Wk : Wv;
    float v = W[(h * DD + d) * HDD + e];
    __nv_bfloat16 hi, lo; split_bf16(v, hi, lo);
    g_Wqkv_hi[(size_t)j * DD + d] = hi;
    g_Wqkv_lo[(size_t)j * DD + d] = lo;
    if (d == 0) {
        const float* bb = (part == 0) ? bq : (part == 1) ? bk : bv;
        g_bp[j] = bb[jj];
    }
}
// W[K][N] fp32 -> out[N][K] split bf16
__global__ void tcvt(const float* __restrict__ W, __nv_bfloat16* __restrict__ Ohi,
                     __nv_bfloat16* __restrict__ Olo, int K, int N)
{
    int idx = blockIdx.x * 256 + threadIdx.x;
    if (idx >= K * N) return;
    int n = idx / K;
    int k = idx - n * K;
    float v = W[(size_t)k * N + n];
    __nv_bfloat16 hi, lo; split_bf16(v, hi, lo);
    Ohi[(size_t)n * K + k] = hi;
    Olo[(size_t)n * K + k] = lo;
}

// ================= layer norm (writes split bf16) =================
__global__ void ln_kernel(const float* __restrict__ x, const float* __restrict__ g,
                          const float* __restrict__ b, __nv_bfloat16* __restrict__ yhi,
                          __nv_bfloat16* __restrict__ ylo)
{
    int row = blockIdx.x;
    int tid = threadIdx.x;
    const float* xr = x + (size_t)row * DD;
    float v0 = xr[tid], v1 = xr[tid + 256], v2 = xr[tid + 512];
    float s  = v0 + v1 + v2;
    float ss = v0 * v0 + v1 * v1 + v2 * v2;
    #pragma unroll
    for (int o = 16; o >= 1; o >>= 1) {
        s  += __shfl_xor_sync(0xffffffffu, s,  o);
        ss += __shfl_xor_sync(0xffffffffu, ss, o);
    }
    __shared__ float rs[8], rss[8];
    int w = tid >> 5, l = tid & 31;
    if (l == 0) { rs[w] = s; rss[w] = ss; }
    __syncthreads();
    float S = 0.f, S2 = 0.f;
    #pragma unroll
    for (int i = 0; i < 8; i++) { S += rs[i]; S2 += rss[i]; }
    float mu  = S  * (1.0f / DD);
    float var = S2 * (1.0f / DD) - mu * mu;
    float inv = rsqrtf(var + 1e-5f);
    #pragma unroll
    for (int q = 0; q < 3; q++) {
        int c = tid + q * 256;
        float v = (q == 0 ? v0 : q == 1 ? v1 : v2);
        float y = (v - mu) * inv * g[c] + b[c];
        __nv_bfloat16 hi, lo; split_bf16(y, hi, lo);
        yhi[(size_t)row * DD + c] = hi;
        ylo[(size_t)row * DD + c] = lo;
    }
}

// ================ mma.sync GEMM: C[M,N] = A[M,K] @ Bt[N,K]^T ================
// A,B as bf16 hi/lo splits. CTA tile 128x128, 8 warps (4m x 2n), warp 32x64.
// K-chunk 32, 3-stage cp.async pipeline.
// Smem stage layout: Ahi[128][32] | Alo | Bhi[128][32] | Blo  (8KB each)
// Swizzle: 16B chunk c of row r stored at chunk (c ^ ((r>>1)&3)).
#define STAGE_B  32768
#define GEMM_SMEM (3*STAGE_B)

template<int ACT, int OSPLIT>
__global__ __launch_bounds__(256)
void tgemm(const __nv_bfloat16* __restrict__ Ahi, const __nv_bfloat16* __restrict__ Alo,
           const __nv_bfloat16* __restrict__ Bhi, const __nv_bfloat16* __restrict__ Blo,
           const float* __restrict__ bias,
           float* __restrict__ Cf, __nv_bfloat16* __restrict__ Chi,
           __nv_bfloat16* __restrict__ Clo, int N, int K)
{
    extern __shared__ char smem[];
    uint32_t ST = smem_u32(smem);
    int tid = threadIdx.x;
    int lane = tid & 31, wid = tid >> 5;
    int wr = wid & 3, wc = wid >> 2;          // warp grid 4 x 2
    int m0 = blockIdx.y * 128;
    int n0 = blockIdx.x * 128;
    int nc = K >> 5;                           // K chunks of 32

    const __nv_bfloat16* Abase_h = Ahi + (size_t)m0 * K;
    const __nv_bfloat16* Abase_l = Alo + (size_t)m0 * K;
    const __nv_bfloat16* Bbase_h = Bhi + (size_t)n0 * K;
    const __nv_bfloat16* Bbase_l = Blo + (size_t)n0 * K;

    auto load_chunk = [&](int c, int p) {
        uint32_t base = ST + p * STAGE_B;
        const __nv_bfloat16* ah = Abase_h + c * 32;
        const __nv_bfloat16* al = Abase_l + c * 32;
        const __nv_bfloat16* bh = Bbase_h + c * 32;
        const __nv_bfloat16* bl = Bbase_l + c * 32;
        #pragma unroll
        for (int j = 0; j < 2; j++) {
            int id = tid + 256 * j;            // 0..511 : 128 rows x 4 chunks
            int r = id >> 2, cc = id & 3;
            uint32_t off = (uint32_t)(r * 64 + ((cc ^ ((r >> 1) & 3)) << 4));
            const size_t go = (size_t)r * K + cc * 8;
            CP16(base +         off, ah + go);
            CP16(base +  8192 + off, al + go);
            CP16(base + 16384 + off, bh + go);
            CP16(base + 24576 + off, bl + go);
        }
    };

    float acc[2][8][4];
    #pragma unroll
    for (int s = 0; s < 2; s++)
        #pragma unroll
        for (int t = 0; t < 8; t++)
            #pragma unroll
            for (int q = 0; q < 4; q++) acc[s][t][q] = 0.f;

    load_chunk(0, 0); CP_COMMIT();
    load_chunk(1, 1); CP_COMMIT();
    load_chunk(2, 2); CP_COMMIT();

    // per-lane ldmatrix row indices
    int arow = wr * 32 + (lane & 15);          // + sub*16
    int brow = wc * 64 + (lane & 15);          // + nh*16
    int khalf = lane >> 4;                     // 0/1

    for (int c = 0; c < nc; c++) {
        CP_WAIT(2);
        __syncthreads();
        uint32_t base = ST + (c % 3) * STAGE_B;
        uint32_t Ah = base, Al = base + 8192, Bh = base + 16384, Bl = base + 24576;
        #pragma unroll
        for (int ks = 0; ks < 2; ks++) {
            uint32_t ahf[2][4], alf[2][4];
            #pragma unroll
            for (int sub = 0; sub < 2; sub++) {
                int r = arow + sub * 16;
                int kc = ks * 2 + khalf;
                uint32_t off = (uint32_t)(r * 64 + ((kc ^ ((r >> 1) & 3)) << 4));
                LDM4(ahf[sub], Ah + off);
                LDM4(alf[sub], Al + off);
            }
            #pragma unroll
            for (int nh = 0; nh < 4; nh++) {
                int n = brow + nh * 16;
                int kc = ks * 2 + khalf;
                uint32_t off = (uint32_t)(n * 64 + ((kc ^ ((n >> 1) & 3)) << 4));
                uint32_t bhf[4], blf[4];
                LDM4(bhf, Bh + off);
                LDM4(blf, Bl + off);
                #pragma unroll
                for (int sub = 0; sub < 2; sub++) {
                    #pragma unroll
                    for (int nt = 0; nt < 2; nt++) {
                        float* d = acc[sub][nh * 2 + nt];
                        MMA16816(d, ahf[sub], bhf[nt], bhf[nt + 2]);
                        MMA16816(d, ahf[sub], blf[nt], blf[nt + 2]);
                        MMA16816(d, alf[sub], bhf[nt], bhf[nt + 2]);
                    }
                }
            }
        }
        __syncthreads();
        if (c + 3 < nc) load_chunk(c + 3, c % 3);
        CP_COMMIT();
    }

    // ---------------- epilogue ----------------
    int g = lane >> 2, t = lane & 3;
    #pragma unroll
    for (int sub = 0; sub < 2; sub++) {
        #pragma unroll
        for (int nt8 = 0; nt8 < 8; nt8++) {
            int col = n0 + wc * 64 + nt8 * 8 + t * 2;
            float b0 = bias[col], b1 = bias[col + 1];
            #pragma unroll
            for (int half = 0; half < 2; half++) {
                int row = m0 + wr * 32 + sub * 16 + g + half * 8;
                float v0 = acc[sub][nt8][half * 2 + 0] + b0;
                float v1 = acc[sub][nt8][half * 2 + 1] + b1;
                if (ACT) { v0 = gelu_exact(v0); v1 = gelu_exact(v1); }
                if (OSPLIT) {
                    __nv_bfloat16 h0, l0, h1, l1;
                    split_bf16(v0, h0, l0); split_bf16(v1, h1, l1);
                    *(__nv_bfloat162*)(Chi + (size_t)row * N + col) = __halves2bfloat162(h0, h1);
                    *(__nv_bfloat162*)(Clo + (size_t)row * N + col) = __halves2bfloat162(l0, l1);
                } else {
                    float2 fv; fv.x = v0; fv.y = v1;
                    *(float2*)(Cf + (size_t)row * N + col) = fv;
                }
            }
        }
    }
}

// ================= flash attention (fp32, 64x64 tiles) =================
__device__ __forceinline__ int swz4(int d)          { return (d + (d >> 2)) & 15; }
__device__ __forceinline__ int tr_idx(int d, int r) { return d * 64 + ((((r >> 2) ^ swz4(d)) & 15) << 2) + (r & 3); }

__global__ __launch_bounds__(256)
void attn_kernel(const float* __restrict__ qkv, __nv_bfloat16* __restrict__ ohi,
                 __nv_bfloat16* __restrict__ olo)
{
    __shared__ float QsT[64 * 64];
    __shared__ float KsT[64 * 64];
    __shared__ float Vs [64 * 64];

    int bh = blockIdx.y;
    int b = bh / HH, h = bh - b * HH;
    int q0 = blockIdx.x * 64;
    int tid = threadIdx.x;
    int tx = tid & 15, ty = tid >> 4;

    const float* qb = qkv + (size_t)b * SS * NC + h * 64;
    const float* kb = qb + 768;
    const float* vb = qb + 1536;

    for (int idx = tid; idx < 1024; idx += 256) {
        int r = idx >> 4;
        int dbase = (idx & 15) << 2;
        float4 v = *(const float4*)(qb + (size_t)(q0 + r) * NC + dbase);
        QsT[tr_idx(dbase + 0, r)] = v.x * 0.125f;
        QsT[tr_idx(dbase + 1, r)] = v.y * 0.125f;
        QsT[tr_idx(dbase + 2, r)] = v.z * 0.125f;
        QsT[tr_idx(dbase + 3, r)] = v.w * 0.125f;
    }

    float o[4][4];
    float m[4], lsum[4];
    #pragma unroll
    for (int i = 0; i < 4; i++) {
        m[i] = -1e30f; lsum[i] = 0.f;
        #pragma unroll
        for (int j = 0; j < 4; j++) o[i][j] = 0.f;
    }

    for (int kt = 0; kt < SS / 64; kt++) {
        __syncthreads();
        int k0 = kt * 64;
        for (int idx = tid; idx < 1024; idx += 256) {
            int r = idx >> 4;
            int dbase = (idx & 15) << 2;
            float4 kv = *(const float4*)(kb + (size_t)(k0 + r) * NC + dbase);
            KsT[tr_idx(dbase + 0, r)] = kv.x;
            KsT[tr_idx(dbase + 1, r)] = kv.y;
            KsT[tr_idx(dbase + 2, r)] = kv.z;
            KsT[tr_idx(dbase + 3, r)] = kv.w;
            float4 vv = *(const float4*)(vb + (size_t)(k0 + r) * NC + dbase);
            *(float4*)&Vs[r * 64 + dbase] = vv;
        }
        __syncthreads();

        float s[4][4];
        #pragma unroll
        for (int i = 0; i < 4; i++)
            #pragma unroll
            for (int j = 0; j < 4; j++) s[i][j] = 0.f;
        #pragma unroll
        for (int d = 0; d < 64; d++) {
            int c = swz4(d);
            float4 ra = *(const float4*)&QsT[d * 64 + ((ty ^ c) << 2)];
            float4 rb = *(const float4*)&KsT[d * 64 + ((tx ^ c) << 2)];
            float qa[4] = {ra.x, ra.y, ra.z, ra.w};
            float ka[4] = {rb.x, rb.y, rb.z, rb.w};
            #pragma unroll
            for (int i = 0; i < 4; i++)
                #pragma unroll
                for (int j = 0; j < 4; j++)
                    s[i][j] = fmaf(qa[i], ka[j], s[i][j]);
        }

        float tmax[4];
        #pragma unroll
        for (int i = 0; i < 4; i++) {
            float t = fmaxf(fmaxf(s[i][0], s[i][1]), fmaxf(s[i][2], s[i][3]));
            #pragma unroll
            for (int off = 8; off >= 1; off >>= 1)
                t = fmaxf(t, __shfl_xor_sync(0xffffffffu, t, off));
            tmax[i] = t;
        }
        float alpha[4];
        #pragma unroll
        for (int i = 0; i < 4; i++) {
            float mn = fmaxf(m[i], tmax[i]);
            alpha[i] = __expf(m[i] - mn);
            m[i] = mn;
        }
        float rsum[4];
        #pragma unroll
        for (int i = 0; i < 4; i++) {
            float acc = 0.f;
            #pragma unroll
            for (int j = 0; j < 4; j++) {
                float p = __expf(s[i][j] - m[i]);
                s[i][j] = p;
                acc += p;
            }
            #pragma unroll
            for (int off = 8; off >= 1; off >>= 1)
                acc += __shfl_xor_sync(0xffffffffu, acc, off);
            rsum[i] = acc;
        }
        #pragma unroll
        for (int i = 0; i < 4; i++) {
            lsum[i] = lsum[i] * alpha[i] + rsum[i];
            #pragma unroll
            for (int j = 0; j < 4; j++) o[i][j] *= alpha[i];
        }

        __syncthreads();
        #pragma unroll
        for (int i = 0; i < 4; i++)
            #pragma unroll
            for (int j = 0; j < 4; j++)
                KsT[tr_idx((tx << 2) + j, (ty << 2) + i)] = s[i][j];
        __syncthreads();

        #pragma unroll
        for (int k = 0; k < 64; k++) {
            int c = swz4(k);
            float4 pa = *(const float4*)&KsT[k * 64 + ((ty ^ c) << 2)];
            float4 vv = *(const float4*)&Vs[k * 64 + (tx << 2)];
            float pv[4] = {pa.x, pa.y, pa.z, pa.w};
            float vr[4] = {vv.x, vv.y, vv.z, vv.w};
            #pragma unroll
            for (int i = 0; i < 4; i++)
                #pragma unroll
                for (int j = 0; j < 4; j++)
                    o[i][j] = fmaf(pv[i], vr[j], o[i][j]);
        }
    }

    #pragma unroll
    for (int i = 0; i < 4; i++) {
        int row = q0 + (ty << 2) + i;
        float inv = 1.0f / lsum[i];
        size_t base = (size_t)(b * SS + row) * DD + h * 64 + (tx << 2);
        float v0 = o[i][0] * inv, v1 = o[i][1] * inv;
        float v2 = o[i][2] * inv, v3 = o[i][3] * inv;
        __nv_bfloat16 h0,l0,h1,l1,h2,l2,h3,l3;
        split_bf16(v0,h0,l0); split_bf16(v1,h1,l1);
        split_bf16(v2,h2,l2); split_bf16(v3,h3,l3);
        *(__nv_bfloat162*)(ohi + base)     = __halves2bfloat162(h0, h1);
        *(__nv_bfloat162*)(ohi + base + 2) = __halves2bfloat162(h2, h3);
        *(__nv_bfloat162*)(olo + base)     = __halves2bfloat162(l0, l1);
        *(__nv_bfloat162*)(olo + base + 2) = __halves2bfloat162(l2, l3);
    }
}

// ================= launch =================
extern "C" void kernel_launch(void* const* d_in, const int* in_sizes, int n_in,
                              void* d_out, int out_size)
{
    const float* x   = (const float*)d_in[0];
    const float* Wq  = (const float*)d_in[1];
    const float* bq  = (const float*)d_in[2];
    const float* Wk  = (const float*)d_in[3];
    const float* bk  = (const float*)d_in[4];
    const float* Wv  = (const float*)d_in[5];
    const float* bv  = (const float*)d_in[6];
    const float* Wo  = (const float*)d_in[7];
    const float* bo  = (const float*)d_in[8];
    const float* W1  = (const float*)d_in[9];
    const float* b1  = (const float*)d_in[10];
    const float* W2  = (const float*)d_in[11];
    const float* b2  = (const float*)d_in[12];
    const float* g1  = (const float*)d_in[13];
    const float* be1 = (const float*)d_in[14];
    const float* g2  = (const float*)d_in[15];
    const float* be2 = (const float*)d_in[16];
    float* out = (float*)d_out;

    void *pqkv, *pa, *pbp, *phh, *phl, *poh, *pol, *pfh, *pfl;
    void *pWqh, *pWql, *pWoh, *pWol, *pW1h, *pW1l, *pW2h, *pW2l;
    cudaGetSymbolAddress(&pqkv, g_qkv);
    cudaGetSymbolAddress(&pa,   g_a);
    cudaGetSymbolAddress(&pbp,  g_bp);
    cudaGetSymbolAddress(&phh,  g_h_hi);  cudaGetSymbolAddress(&phl, g_h_lo);
    cudaGetSymbolAddress(&poh,  g_o_hi);  cudaGetSymbolAddress(&pol, g_o_lo);
    cudaGetSymbolAddress(&pfh,  g_f_hi);  cudaGetSymbolAddress(&pfl, g_f_lo);
    cudaGetSymbolAddress(&pWqh, g_Wqkv_hi); cudaGetSymbolAddress(&pWql, g_Wqkv_lo);
    cudaGetSymbolAddress(&pWoh, g_Wo_hi);   cudaGetSymbolAddress(&pWol, g_Wo_lo);
    cudaGetSymbolAddress(&pW1h, g_W1_hi);   cudaGetSymbolAddress(&pW1l, g_W1_lo);
    cudaGetSymbolAddress(&pW2h, g_W2_hi);   cudaGetSymbolAddress(&pW2l, g_W2_lo);
    float* qkv = (float*)pqkv;
    float* a   = (float*)pa;
    float* bp  = (float*)pbp;
    __nv_bfloat16* hh = (__nv_bfloat16*)phh, *hl = (__nv_bfloat16*)phl;
    __nv_bfloat16* oh = (__nv_bfloat16*)poh, *ol = (__nv_bfloat16*)pol;
    __nv_bfloat16* fh = (__nv_bfloat16*)pfh, *fl = (__nv_bfloat16*)pfl;
    __nv_bfloat16* Wqh = (__nv_bfloat16*)pWqh, *Wql = (__nv_bfloat16*)pWql;
    __nv_bfloat16* Woh = (__nv_bfloat16*)pWoh, *Wol = (__nv_bfloat16*)pWol;
    __nv_bfloat16* W1h = (__nv_bfloat16*)pW1h, *W1l = (__nv_bfloat16*)pW1l;
    __nv_bfloat16* W2h = (__nv_bfloat16*)pW2h, *W2l = (__nv_bfloat16*)pW2l;

    cudaFuncSetAttribute(tgemm<0,0>, cudaFuncAttributeMaxDynamicSharedMemorySize, GEMM_SMEM);
    cudaFuncSetAttribute(tgemm<1,1>, cudaFuncAttributeMaxDynamicSharedMemorySize, GEMM_SMEM);

    // weight prep
    qkv_cvt<<<(NC * DD + 255) / 256, 256>>>(Wq, Wk, Wv, bq, bk, bv);
    tcvt<<<(DD * DD + 255) / 256, 256>>>(Wo, Woh, Wol, DD, DD);
    tcvt<<<(DD * FF + 255) / 256, 256>>>(W1, W1h, W1l, DD, FF);
    tcvt<<<(FF * DD + 255) / 256, 256>>>(W2, W2h, W2l, FF, DD);
    // LN1 -> split
    ln_kernel<<<ROWS, 256>>>(x, g1, be1, hh, hl);
    // QKV projection (tensor cores, fp32 out)
    tgemm<0,0><<<dim3(NC / 128, ROWS / 128), 256, GEMM_SMEM>>>(
        hh, hl, Wqh, Wql, bp, qkv, nullptr, nullptr, NC, DD);
    // attention (fp32), writes split bf16
    attn_kernel<<<dim3(SS / 64, BB * HH), 256>>>(qkv, oh, ol);
    // output projection (fp32 out -> LN2 input)
    tgemm<0,0><<<dim3(DD / 128, ROWS / 128), 256, GEMM_SMEM>>>(
        oh, ol, Woh, Wol, bo, a, nullptr, nullptr, DD, DD);
    // LN2 -> split
    ln_kernel<<<ROWS, 256>>>(a, g2, be2, hh, hl);
    // FFN up + GELU -> split
    tgemm<1,1><<<dim3(FF / 128, ROWS / 128), 256, GEMM_SMEM>>>(
        hh, hl, W1h, W1l, b1, nullptr, fh, fl, FF, DD);
    // FFN down -> output (fp32)
    tgemm<0,0><<<dim3(DD / 128, ROWS / 128), 256, GEMM_SMEM>>>(
        fh, fl, W2h, W2l, b2, out, nullptr, nullptr, DD, FF);
}

// round 6
// speedup vs baseline: 2.4397x; 1.5830x over previous
#include <cuda_runtime.h>
#include <cuda_bf16.h>
#include <math.h>
#include <stdint.h>

// Problem constants
#define BB   4
#define SS   2048
#define DD   768
#define HH   12
#define HDD  64
#define FF   3072
#define ROWS (BB*SS)   // 8192
#define NC   2304      // 3*DD packed qkv cols

// ---------------- scratch (device globals; no runtime allocation) ----------
__device__ float g_a  [ROWS*DD];                 // after Wo (fp32, LN2 input)
__device__ float g_bp [NC];                      // packed QKV bias
__device__ __align__(256) __nv_bfloat16 g_h_hi[ROWS*DD], g_h_lo[ROWS*DD];
__device__ __align__(256) __nv_bfloat16 g_qkvh[ROWS*NC], g_qkvl[ROWS*NC];   // split qkv
__device__ __align__(256) __nv_bfloat16 g_o_hi[ROWS*DD], g_o_lo[ROWS*DD];
__device__ __align__(256) __nv_bfloat16 g_f_hi[ROWS*FF], g_f_lo[ROWS*FF];
__device__ __align__(256) __nv_bfloat16 g_Wqkv_hi[NC*DD], g_Wqkv_lo[NC*DD]; // [2304][768]
__device__ __align__(256) __nv_bfloat16 g_Wo_hi[DD*DD],  g_Wo_lo[DD*DD];    // [768][768]
__device__ __align__(256) __nv_bfloat16 g_W1_hi[FF*DD],  g_W1_lo[FF*DD];    // [3072][768]
__device__ __align__(256) __nv_bfloat16 g_W2_hi[DD*FF],  g_W2_lo[DD*FF];    // [768][3072]

// ================= PTX helpers (baseline ISA only: sm_80-class) =============
__device__ __forceinline__ uint32_t smem_u32(const void* p) {
    uint32_t a;
    asm("{ .reg .u64 t; cvta.to.shared.u64 t, %1; cvt.u32.u64 %0, t; }" : "=r"(a) : "l"(p));
    return a;
}
#define CP16(dst, src) asm volatile("cp.async.cg.shared.global [%0], [%1], 16;" :: "r"(dst), "l"(src))
#define CP_COMMIT()    asm volatile("cp.async.commit_group;" ::: "memory")
#define CP_WAIT(n)     asm volatile("cp.async.wait_group %0;" :: "n"(n) : "memory")

#define LDM4(r, addr) \
    asm volatile("ldmatrix.sync.aligned.m8n8.x4.shared.b16 {%0,%1,%2,%3}, [%4];" \
        : "=r"((r)[0]), "=r"((r)[1]), "=r"((r)[2]), "=r"((r)[3]) : "r"(addr))
#define LDM4T(r, addr) \
    asm volatile("ldmatrix.sync.aligned.m8n8.x4.trans.shared.b16 {%0,%1,%2,%3}, [%4];" \
        : "=r"((r)[0]), "=r"((r)[1]), "=r"((r)[2]), "=r"((r)[3]) : "r"(addr))

#define MMA16816(d, a, b0v, b1v) \
    asm volatile("mma.sync.aligned.m16n8k16.row.col.f32.bf16.bf16.f32 " \
        "{%0,%1,%2,%3},{%4,%5,%6,%7},{%8,%9},{%0,%1,%2,%3};" \
        : "+f"((d)[0]), "+f"((d)[1]), "+f"((d)[2]), "+f"((d)[3]) \
        : "r"((a)[0]), "r"((a)[1]), "r"((a)[2]), "r"((a)[3]), "r"(b0v), "r"(b1v))

__device__ __forceinline__ void split_bf16(float v, __nv_bfloat16& hi, __nv_bfloat16& lo) {
    hi = __float2bfloat16(v);
    lo = __float2bfloat16(v - __bfloat162float(hi));
}
__device__ __forceinline__ uint32_t pack_bf2(float a, float b) {
    __nv_bfloat162 t = __halves2bfloat162(__float2bfloat16(a), __float2bfloat16(b));
    return *(uint32_t*)&t;
}
__device__ __forceinline__ float gelu_exact(float x) {
    return 0.5f * x * (1.0f + erff(x * 0.70710678118654752f));
}

// ================= weight conversion =================
__global__ void qkv_cvt(const float* __restrict__ Wq, const float* __restrict__ Wk,
                        const float* __restrict__ Wv, const float* __restrict__ bq,
                        const float* __restrict__ bk, const float* __restrict__ bv)
{
    int idx = blockIdx.x * 256 + threadIdx.x;     // over NC*DD
    if (idx >= NC * DD) return;
    int j = idx / DD;                              // out row: part*768 + h*64 + e
    int d = idx - j * DD;
    int part = j / DD;
    int jj = j - part * DD;
    int h = jj >> 6, e = jj & 63;
    const float* W = (part == 0) ? Wq : (part == 1) ? Wk : Wv;
    float v = W[(h * DD + d) * HDD + e];
    __nv_bfloat16 hi, lo; split_bf16(v, hi, lo);
    g_Wqkv_hi[(size_t)j * DD + d] = hi;
    g_Wqkv_lo[(size_t)j * DD + d] = lo;
    if (d == 0) {
        const float* bb = (part == 0) ? bq : (part == 1) ? bk : bv;
        g_bp[j] = bb[jj];
    }
}
// W[K][N] fp32 -> out[N][K] split bf16
__global__ void tcvt(const float* __restrict__ W, __nv_bfloat16* __restrict__ Ohi,
                     __nv_bfloat16* __restrict__ Olo, int K, int N)
{
    int idx = blockIdx.x * 256 + threadIdx.x;
    if (idx >= K * N) return;
    int n = idx / K;
    int k = idx - n * K;
    float v = W[(size_t)k * N + n];
    __nv_bfloat16 hi, lo; split_bf16(v, hi, lo);
    Ohi[(size_t)n * K + k] = hi;
    Olo[(size_t)n * K + k] = lo;
}

// ================= layer norm (writes split bf16) =================
__global__ void ln_kernel(const float* __restrict__ x, const float* __restrict__ g,
                          const float* __restrict__ b, __nv_bfloat16* __restrict__ yhi,
                          __nv_bfloat16* __restrict__ ylo)
{
    int row = blockIdx.x;
    int tid = threadIdx.x;
    const float* xr = x + (size_t)row * DD;
    float v0 = xr[tid], v1 = xr[tid + 256], v2 = xr[tid + 512];
    float s  = v0 + v1 + v2;
    float ss = v0 * v0 + v1 * v1 + v2 * v2;
    #pragma unroll
    for (int o = 16; o >= 1; o >>= 1) {
        s  += __shfl_xor_sync(0xffffffffu, s,  o);
        ss += __shfl_xor_sync(0xffffffffu, ss, o);
    }
    __shared__ float rs[8], rss[8];
    int w = tid >> 5, l = tid & 31;
    if (l == 0) { rs[w] = s; rss[w] = ss; }
    __syncthreads();
    float S = 0.f, S2 = 0.f;
    #pragma unroll
    for (int i = 0; i < 8; i++) { S += rs[i]; S2 += rss[i]; }
    float mu  = S  * (1.0f / DD);
    float var = S2 * (1.0f / DD) - mu * mu;
    float inv = rsqrtf(var + 1e-5f);
    #pragma unroll
    for (int q = 0; q < 3; q++) {
        int c = tid + q * 256;
        float v = (q == 0 ? v0 : q == 1 ? v1 : v2);
        float y = (v - mu) * inv * g[c] + b[c];
        __nv_bfloat16 hi, lo; split_bf16(y, hi, lo);
        yhi[(size_t)row * DD + c] = hi;
        ylo[(size_t)row * DD + c] = lo;
    }
}

// ================ mma.sync GEMM: C[M,N] = A[M,K] @ Bt[N,K]^T ================
#define STAGE_B  32768
#define GEMM_SMEM (3*STAGE_B)

template<int ACT, int OSPLIT>
__global__ __launch_bounds__(256)
void tgemm(const __nv_bfloat16* __restrict__ Ahi, const __nv_bfloat16* __restrict__ Alo,
           const __nv_bfloat16* __restrict__ Bhi, const __nv_bfloat16* __restrict__ Blo,
           const float* __restrict__ bias,
           float* __restrict__ Cf, __nv_bfloat16* __restrict__ Chi,
           __nv_bfloat16* __restrict__ Clo, int N, int K)
{
    extern __shared__ char smem[];
    uint32_t ST = smem_u32(smem);
    int tid = threadIdx.x;
    int lane = tid & 31, wid = tid >> 5;
    int wr = wid & 3, wc = wid >> 2;          // warp grid 4 x 2
    int m0 = blockIdx.y * 128;
    int n0 = blockIdx.x * 128;
    int nc = K >> 5;                           // K chunks of 32

    const __nv_bfloat16* Abase_h = Ahi + (size_t)m0 * K;
    const __nv_bfloat16* Abase_l = Alo + (size_t)m0 * K;
    const __nv_bfloat16* Bbase_h = Bhi + (size_t)n0 * K;
    const __nv_bfloat16* Bbase_l = Blo + (size_t)n0 * K;

    auto load_chunk = [&](int c, int p) {
        uint32_t base = ST + p * STAGE_B;
        const __nv_bfloat16* ah = Abase_h + c * 32;
        const __nv_bfloat16* al = Abase_l + c * 32;
        const __nv_bfloat16* bh = Bbase_h + c * 32;
        const __nv_bfloat16* bl = Bbase_l + c * 32;
        #pragma unroll
        for (int j = 0; j < 2; j++) {
            int id = tid + 256 * j;            // 0..511 : 128 rows x 4 chunks
            int r = id >> 2, cc = id & 3;
            uint32_t off = (uint32_t)(r * 64 + ((cc ^ ((r >> 1) & 3)) << 4));
            const size_t go = (size_t)r * K + cc * 8;
            CP16(base +         off, ah + go);
            CP16(base +  8192 + off, al + go);
            CP16(base + 16384 + off, bh + go);
            CP16(base + 24576 + off, bl + go);
        }
    };

    float acc[2][8][4];
    #pragma unroll
    for (int s = 0; s < 2; s++)
        #pragma unroll
        for (int t = 0; t < 8; t++)
            #pragma unroll
            for (int q = 0; q < 4; q++) acc[s][t][q] = 0.f;

    load_chunk(0, 0); CP_COMMIT();
    load_chunk(1, 1); CP_COMMIT();
    load_chunk(2, 2); CP_COMMIT();

    int arow = wr * 32 + (lane & 15);
    int brow = wc * 64 + (lane & 15);
    int khalf = lane >> 4;

    for (int c = 0; c < nc; c++) {
        CP_WAIT(2);
        __syncthreads();
        uint32_t base = ST + (c % 3) * STAGE_B;
        uint32_t Ah = base, Al = base + 8192, Bh = base + 16384, Bl = base + 24576;
        #pragma unroll
        for (int ks = 0; ks < 2; ks++) {
            uint32_t ahf[2][4], alf[2][4];
            #pragma unroll
            for (int sub = 0; sub < 2; sub++) {
                int r = arow + sub * 16;
                int kc = ks * 2 + khalf;
                uint32_t off = (uint32_t)(r * 64 + ((kc ^ ((r >> 1) & 3)) << 4));
                LDM4(ahf[sub], Ah + off);
                LDM4(alf[sub], Al + off);
            }
            #pragma unroll
            for (int nh = 0; nh < 4; nh++) {
                int n = brow + nh * 16;
                int kc = ks * 2 + khalf;
                uint32_t off = (uint32_t)(n * 64 + ((kc ^ ((n >> 1) & 3)) << 4));
                uint32_t bhf[4], blf[4];
                LDM4(bhf, Bh + off);
                LDM4(blf, Bl + off);
                #pragma unroll
                for (int sub = 0; sub < 2; sub++) {
                    #pragma unroll
                    for (int nt = 0; nt < 2; nt++) {
                        float* d = acc[sub][nh * 2 + nt];
                        MMA16816(d, ahf[sub], bhf[nt], bhf[nt + 2]);
                        MMA16816(d, ahf[sub], blf[nt], blf[nt + 2]);
                        MMA16816(d, alf[sub], bhf[nt], bhf[nt + 2]);
                    }
                }
            }
        }
        __syncthreads();
        if (c + 3 < nc) load_chunk(c + 3, c % 3);
        CP_COMMIT();
    }

    // ---------------- epilogue ----------------
    int g = lane >> 2, t = lane & 3;
    #pragma unroll
    for (int sub = 0; sub < 2; sub++) {
        #pragma unroll
        for (int nt8 = 0; nt8 < 8; nt8++) {
            int col = n0 + wc * 64 + nt8 * 8 + t * 2;
            float b0 = bias[col], b1 = bias[col + 1];
            #pragma unroll
            for (int half = 0; half < 2; half++) {
                int row = m0 + wr * 32 + sub * 16 + g + half * 8;
                float v0 = acc[sub][nt8][half * 2 + 0] + b0;
                float v1 = acc[sub][nt8][half * 2 + 1] + b1;
                if (ACT) { v0 = gelu_exact(v0); v1 = gelu_exact(v1); }
                if (OSPLIT) {
                    __nv_bfloat16 h0, l0, h1, l1;
                    split_bf16(v0, h0, l0); split_bf16(v1, h1, l1);
                    *(__nv_bfloat162*)(Chi + (size_t)row * N + col) = __halves2bfloat162(h0, h1);
                    *(__nv_bfloat162*)(Clo + (size_t)row * N + col) = __halves2bfloat162(l0, l1);
                } else {
                    float2 fv; fv.x = v0; fv.y = v1;
                    *(float2*)(Cf + (size_t)row * N + col) = fv;
                }
            }
        }
    }
}

// ============ tensor-core flash attention (bf16 split, 64x64 tiles) =========
// Smem: Qhi 8K | Qlo 8K | 2 stages x (Khi 8K | Klo 8K | Vhi 8K | Vlo 8K)
// Tile layout: 64 rows x 64 bf16 (128B rows, 8x16B chunks), chunk swizzled c^(r&7).
#define ATT_STAGE 32768
#define ATT_SMEM  (16384 + 2*ATT_STAGE)

__device__ __forceinline__ uint32_t aoff(int r, int c) {
    return (uint32_t)((r << 7) + (((c ^ (r & 7)) & 7) << 4));
}

__global__ __launch_bounds__(128)
void attn_tc(const __nv_bfloat16* __restrict__ qh, const __nv_bfloat16* __restrict__ ql,
             __nv_bfloat16* __restrict__ ohi, __nv_bfloat16* __restrict__ olo)
{
    extern __shared__ char sm[];
    uint32_t S0 = smem_u32(sm);
    const uint32_t Qh = S0, Ql = S0 + 8192;
    int tid = threadIdx.x, lane = tid & 31, wid = tid >> 5;
    int bh = blockIdx.y, b = bh / HH, h = bh - b * HH;
    int q0 = blockIdx.x * 64;
    size_t rowbase = (size_t)b * SS * NC + h * 64;

    // Q load (hi/lo)
    {
        const __nv_bfloat16* qph = qh + rowbase + (size_t)q0 * NC;
        const __nv_bfloat16* qpl = ql + rowbase + (size_t)q0 * NC;
        #pragma unroll
        for (int j = 0; j < 4; j++) {
            int id = tid + 128 * j; int r = id >> 3, c = id & 7;
            size_t go = (size_t)r * NC + c * 8;
            CP16(Qh + aoff(r, c), qph + go);
            CP16(Ql + aoff(r, c), qpl + go);
        }
        CP_COMMIT();
    }
    auto load_kv = [&](int kt, int p) {
        uint32_t base = S0 + 16384 + p * ATT_STAGE;
        size_t kb = rowbase + (size_t)(kt * 64) * NC + 768;
        size_t vb = kb + 768;
        #pragma unroll
        for (int j = 0; j < 4; j++) {
            int id = tid + 128 * j; int r = id >> 3, c = id & 7;
            uint32_t o_ = aoff(r, c);
            size_t go = (size_t)r * NC + c * 8;
            CP16(base +         o_, qh + kb + go);
            CP16(base +  8192 + o_, ql + kb + go);
            CP16(base + 16384 + o_, qh + vb + go);
            CP16(base + 24576 + o_, ql + vb + go);
        }
        CP_COMMIT();
    };
    load_kv(0, 0);
    load_kv(1, 1);

    float o[8][4];
    #pragma unroll
    for (int i = 0; i < 8; i++)
        #pragma unroll
        for (int q = 0; q < 4; q++) o[i][q] = 0.f;
    float m0r = -1e30f, m1r = -1e30f, l0r = 0.f, l1r = 0.f;
    int g = lane >> 2, t = lane & 3;
    int arow = wid * 16 + (lane & 15);
    int khalf = lane >> 4;

    for (int kt = 0; kt < SS / 64; kt++) {
        int p = kt & 1;
        CP_WAIT(1);
        __syncthreads();
        uint32_t base = S0 + 16384 + p * ATT_STAGE;
        uint32_t Kh = base, Kl = base + 8192, Vh = base + 16384, Vl = base + 24576;

        // ---- S = (Qhi+Qlo)(Khi+Klo)^T, 3-term split ----
        float s[8][4];
        #pragma unroll
        for (int i = 0; i < 8; i++)
            #pragma unroll
            for (int q = 0; q < 4; q++) s[i][q] = 0.f;
        #pragma unroll
        for (int ks = 0; ks < 4; ks++) {
            uint32_t qah[4], qal[4];
            uint32_t ao = aoff(arow, ks * 2 + khalf);
            LDM4(qah, Qh + ao);
            LDM4(qal, Ql + ao);
            #pragma unroll
            for (int np = 0; np < 4; np++) {
                uint32_t bo = aoff(np * 16 + (lane & 15), ks * 2 + khalf);
                uint32_t kbh[4], kbl[4];
                LDM4(kbh, Kh + bo);
                LDM4(kbl, Kl + bo);
                #pragma unroll
                for (int half = 0; half < 2; half++) {
                    float* d = s[np * 2 + half];
                    MMA16816(d, qah, kbh[half], kbh[half + 2]);
                    MMA16816(d, qah, kbl[half], kbl[half + 2]);
                    MMA16816(d, qal, kbh[half], kbh[half + 2]);
                }
            }
        }
        // ---- online softmax ----
        float mn0 = m0r, mn1 = m1r;
        #pragma unroll
        for (int nb = 0; nb < 8; nb++) {
            s[nb][0] *= 0.125f; s[nb][1] *= 0.125f;
            s[nb][2] *= 0.125f; s[nb][3] *= 0.125f;
            mn0 = fmaxf(mn0, fmaxf(s[nb][0], s[nb][1]));
            mn1 = fmaxf(mn1, fmaxf(s[nb][2], s[nb][3]));
        }
        mn0 = fmaxf(mn0, __shfl_xor_sync(0xffffffffu, mn0, 1));
        mn0 = fmaxf(mn0, __shfl_xor_sync(0xffffffffu, mn0, 2));
        mn1 = fmaxf(mn1, __shfl_xor_sync(0xffffffffu, mn1, 1));
        mn1 = fmaxf(mn1, __shfl_xor_sync(0xffffffffu, mn1, 2));
        float al0 = __expf(m0r - mn0), al1 = __expf(m1r - mn1);
        m0r = mn0; m1r = mn1;
        float sum0 = 0.f, sum1 = 0.f;
        uint32_t ph[4][4], pl[4][4];
        #pragma unroll
        for (int kg = 0; kg < 4; kg++) {
            #pragma unroll
            for (int half = 0; half < 2; half++) {
                int nb = kg * 2 + half;
                float p0 = __expf(s[nb][0] - mn0), p1 = __expf(s[nb][1] - mn0);
                float p2 = __expf(s[nb][2] - mn1), p3 = __expf(s[nb][3] - mn1);
                sum0 += p0 + p1; sum1 += p2 + p3;
                float h0 = __bfloat162float(__float2bfloat16(p0));
                float h1 = __bfloat162float(__float2bfloat16(p1));
                float h2 = __bfloat162float(__float2bfloat16(p2));
                float h3 = __bfloat162float(__float2bfloat16(p3));
                // A-frag: a0={P[g][2t..]}, a1={P[g+8][2t..]}, a2/a3 = k+8 (next nb)
                ph[kg][half * 2 + 0] = pack_bf2(p0, p1);
                ph[kg][half * 2 + 1] = pack_bf2(p2, p3);
                pl[kg][half * 2 + 0] = pack_bf2(p0 - h0, p1 - h1);
                pl[kg][half * 2 + 1] = pack_bf2(p2 - h2, p3 - h3);
            }
        }
        l0r = l0r * al0 + sum0;
        l1r = l1r * al1 + sum1;
        #pragma unroll
        for (int nb = 0; nb < 8; nb++) {
            o[nb][0] *= al0; o[nb][1] *= al0;
            o[nb][2] *= al1; o[nb][3] *= al1;
        }
        // ---- O += P V, 3-term split, V via ldmatrix.trans ----
        #pragma unroll
        for (int kg = 0; kg < 4; kg++) {
            #pragma unroll
            for (int ep = 0; ep < 4; ep++) {
                uint32_t vo = aoff(kg * 16 + (lane & 15), ep * 2 + khalf);
                uint32_t vbh[4], vbl[4];
                LDM4T(vbh, Vh + vo);
                LDM4T(vbl, Vl + vo);
                #pragma unroll
                for (int half = 0; half < 2; half++) {
                    float* d = o[ep * 2 + half];
                    MMA16816(d, ph[kg], vbh[half * 2], vbh[half * 2 + 1]);
                    MMA16816(d, ph[kg], vbl[half * 2], vbl[half * 2 + 1]);
                    MMA16816(d, pl[kg], vbh[half * 2], vbh[half * 2 + 1]);
                }
            }
        }
        __syncthreads();
        if (kt + 2 < SS / 64) load_kv(kt + 2, p);
    }
    // ---- epilogue ----
    l0r += __shfl_xor_sync(0xffffffffu, l0r, 1);
    l0r += __shfl_xor_sync(0xffffffffu, l0r, 2);
    l1r += __shfl_xor_sync(0xffffffffu, l1r, 1);
    l1r += __shfl_xor_sync(0xffffffffu, l1r, 2);
    float inv0 = 1.f / l0r, inv1 = 1.f / l1r;
    int r0 = q0 + wid * 16 + g, r1 = r0 + 8;
    #pragma unroll
    for (int eb = 0; eb < 8; eb++) {
        int col = h * 64 + eb * 8 + t * 2;
        size_t o0 = (size_t)(b * SS + r0) * DD + col;
        size_t o1 = (size_t)(b * SS + r1) * DD + col;
        float v00 = o[eb][0] * inv0, v01 = o[eb][1] * inv0;
        float v10 = o[eb][2] * inv1, v11 = o[eb][3] * inv1;
        __nv_bfloat16 h0, l0, h1, l1, h2, l2, h3, l3;
        split_bf16(v00, h0, l0); split_bf16(v01, h1, l1);
        split_bf16(v10, h2, l2); split_bf16(v11, h3, l3);
        *(__nv_bfloat162*)(ohi + o0) = __halves2bfloat162(h0, h1);
        *(__nv_bfloat162*)(olo + o0) = __halves2bfloat162(l0, l1);
        *(__nv_bfloat162*)(ohi + o1) = __halves2bfloat162(h2, h3);
        *(__nv_bfloat162*)(olo + o1) = __halves2bfloat162(l2, l3);
    }
}

// ================= launch =================
extern "C" void kernel_launch(void* const* d_in, const int* in_sizes, int n_in,
                              void* d_out, int out_size)
{
    const float* x   = (const float*)d_in[0];
    const float* Wq  = (const float*)d_in[1];
    const float* bq  = (const float*)d_in[2];
    const float* Wk  = (const float*)d_in[3];
    const float* bk  = (const float*)d_in[4];
    const float* Wv  = (const float*)d_in[5];
    const float* bv  = (const float*)d_in[6];
    const float* Wo  = (const float*)d_in[7];
    const float* bo  = (const float*)d_in[8];
    const float* W1  = (const float*)d_in[9];
    const float* b1  = (const float*)d_in[10];
    const float* W2  = (const float*)d_in[11];
    const float* b2  = (const float*)d_in[12];
    const float* g1  = (const float*)d_in[13];
    const float* be1 = (const float*)d_in[14];
    const float* g2  = (const float*)d_in[15];
    const float* be2 = (const float*)d_in[16];
    float* out = (float*)d_out;

    void *pa, *pbp, *phh, *phl, *pqh, *pql, *poh, *pol, *pfh, *pfl;
    void *pWqh, *pWql, *pWoh, *pWol, *pW1h, *pW1l, *pW2h, *pW2l;
    cudaGetSymbolAddress(&pa,   g_a);
    cudaGetSymbolAddress(&pbp,  g_bp);
    cudaGetSymbolAddress(&phh,  g_h_hi);  cudaGetSymbolAddress(&phl, g_h_lo);
    cudaGetSymbolAddress(&pqh,  g_qkvh);  cudaGetSymbolAddress(&pql, g_qkvl);
    cudaGetSymbolAddress(&poh,  g_o_hi);  cudaGetSymbolAddress(&pol, g_o_lo);
    cudaGetSymbolAddress(&pfh,  g_f_hi);  cudaGetSymbolAddress(&pfl, g_f_lo);
    cudaGetSymbolAddress(&pWqh, g_Wqkv_hi); cudaGetSymbolAddress(&pWql, g_Wqkv_lo);
    cudaGetSymbolAddress(&pWoh, g_Wo_hi);   cudaGetSymbolAddress(&pWol, g_Wo_lo);
    cudaGetSymbolAddress(&pW1h, g_W1_hi);   cudaGetSymbolAddress(&pW1l, g_W1_lo);
    cudaGetSymbolAddress(&pW2h, g_W2_hi);   cudaGetSymbolAddress(&pW2l, g_W2_lo);
    float* a   = (float*)pa;
    float* bp  = (float*)pbp;
    __nv_bfloat16* hh = (__nv_bfloat16*)phh, *hl = (__nv_bfloat16*)phl;
    __nv_bfloat16* qvh = (__nv_bfloat16*)pqh, *qvl = (__nv_bfloat16*)pql;
    __nv_bfloat16* oh = (__nv_bfloat16*)poh, *ol = (__nv_bfloat16*)pol;
    __nv_bfloat16* fh = (__nv_bfloat16*)pfh, *fl = (__nv_bfloat16*)pfl;
    __nv_bfloat16* Wqh = (__nv_bfloat16*)pWqh, *Wql = (__nv_bfloat16*)pWql;
    __nv_bfloat16* Woh = (__nv_bfloat16*)pWoh, *Wol = (__nv_bfloat16*)pWol;
    __nv_bfloat16* W1h = (__nv_bfloat16*)pW1h, *W1l = (__nv_bfloat16*)pW1l;
    __nv_bfloat16* W2h = (__nv_bfloat16*)pW2h, *W2l = (__nv_bfloat16*)pW2l;

    cudaFuncSetAttribute(tgemm<0,0>, cudaFuncAttributeMaxDynamicSharedMemorySize, GEMM_SMEM);
    cudaFuncSetAttribute(tgemm<0,1>, cudaFuncAttributeMaxDynamicSharedMemorySize, GEMM_SMEM);
    cudaFuncSetAttribute(tgemm<1,1>, cudaFuncAttributeMaxDynamicSharedMemorySize, GEMM_SMEM);
    cudaFuncSetAttribute(attn_tc,    cudaFuncAttributeMaxDynamicSharedMemorySize, ATT_SMEM);

    // weight prep
    qkv_cvt<<<(NC * DD + 255) / 256, 256>>>(Wq, Wk, Wv, bq, bk, bv);
    tcvt<<<(DD * DD + 255) / 256, 256>>>(Wo, Woh, Wol, DD, DD);
    tcvt<<<(DD * FF + 255) / 256, 256>>>(W1, W1h, W1l, DD, FF);
    tcvt<<<(FF * DD + 255) / 256, 256>>>(W2, W2h, W2l, FF, DD);
    // LN1 -> split
    ln_kernel<<<ROWS, 256>>>(x, g1, be1, hh, hl);
    // QKV projection -> split bf16 qkv
    tgemm<0,1><<<dim3(NC / 128, ROWS / 128), 256, GEMM_SMEM>>>(
        hh, hl, Wqh, Wql, bp, nullptr, qvh, qvl, NC, DD);
    // tensor-core flash attention -> split bf16 o
    attn_tc<<<dim3(SS / 64, BB * HH), 128, ATT_SMEM>>>(qvh, qvl, oh, ol);
    // output projection (fp32 out -> LN2 input)
    tgemm<0,0><<<dim3(DD / 128, ROWS / 128), 256, GEMM_SMEM>>>(
        oh, ol, Woh, Wol, bo, a, nullptr, nullptr, DD, DD);
    // LN2 -> split
    ln_kernel<<<ROWS, 256>>>(a, g2, be2, hh, hl);
    // FFN up + GELU -> split
    tgemm<1,1><<<dim3(FF / 128, ROWS / 128), 256, GEMM_SMEM>>>(
        hh, hl, W1h, W1l, b1, nullptr, fh, fl, FF, DD);
    // FFN down -> output (fp32)
    tgemm<0,0><<<dim3(DD / 128, ROWS / 128), 256, GEMM_SMEM>>>(
        fh, fl, W2h, W2l, b2, out, nullptr, nullptr, DD, FF);
}

// round 9
// speedup vs baseline: 2.4992x; 1.0244x over previous
#include <cuda_runtime.h>
#include <cuda_bf16.h>
#include <math.h>
#include <stdint.h>

// Problem constants
#define BB   4
#define SS   2048
#define DD   768
#define HH   12
#define HDD  64
#define FF   3072
#define ROWS (BB*SS)   // 8192
#define NC   2304      // 3*DD packed qkv cols

// ---------------- scratch (device globals; no runtime allocation) ----------
__device__ float g_part[3*(size_t)ROWS*DD];      // split-K fp32 partials (3 planes)
__device__ float g_bp [NC];                      // packed QKV bias
__device__ __align__(256) __nv_bfloat16 g_h_hi[ROWS*DD], g_h_lo[ROWS*DD];
__device__ __align__(256) __nv_bfloat16 g_qkvh[ROWS*NC], g_qkvl[ROWS*NC];   // split qkv
__device__ __align__(256) __nv_bfloat16 g_o_hi[ROWS*DD], g_o_lo[ROWS*DD];
__device__ __align__(256) __nv_bfloat16 g_f_hi[ROWS*FF], g_f_lo[ROWS*FF];
__device__ __align__(256) __nv_bfloat16 g_Wqkv_hi[NC*DD], g_Wqkv_lo[NC*DD]; // [2304][768]
__device__ __align__(256) __nv_bfloat16 g_Wo_hi[DD*DD],  g_Wo_lo[DD*DD];    // [768][768]
__device__ __align__(256) __nv_bfloat16 g_W1_hi[FF*DD],  g_W1_lo[FF*DD];    // [3072][768]
__device__ __align__(256) __nv_bfloat16 g_W2_hi[DD*FF],  g_W2_lo[DD*FF];    // [768][3072]

// ================= PTX helpers (baseline ISA only: sm_80-class) =============
__device__ __forceinline__ uint32_t smem_u32(const void* p) {
    uint32_t a;
    asm("{ .reg .u64 t; cvta.to.shared.u64 t, %1; cvt.u32.u64 %0, t; }" : "=r"(a) : "l"(p));
    return a;
}
#define CP16(dst, src) asm volatile("cp.async.cg.shared.global [%0], [%1], 16;" :: "r"(dst), "l"(src))
#define CP_COMMIT()    asm volatile("cp.async.commit_group;" ::: "memory")
#define CP_WAIT(n)     asm volatile("cp.async.wait_group %0;" :: "n"(n) : "memory")

#define LDM4(r, addr) \
    asm volatile("ldmatrix.sync.aligned.m8n8.x4.shared.b16 {%0,%1,%2,%3}, [%4];" \
        : "=r"((r)[0]), "=r"((r)[1]), "=r"((r)[2]), "=r"((r)[3]) : "r"(addr))
#define LDM4T(r, addr) \
    asm volatile("ldmatrix.sync.aligned.m8n8.x4.trans.shared.b16 {%0,%1,%2,%3}, [%4];" \
        : "=r"((r)[0]), "=r"((r)[1]), "=r"((r)[2]), "=r"((r)[3]) : "r"(addr))

#define MMA16816(d, a, b0v, b1v) \
    asm volatile("mma.sync.aligned.m16n8k16.row.col.f32.bf16.bf16.f32 " \
        "{%0,%1,%2,%3},{%4,%5,%6,%7},{%8,%9},{%0,%1,%2,%3};" \
        : "+f"((d)[0]), "+f"((d)[1]), "+f"((d)[2]), "+f"((d)[3]) \
        : "r"((a)[0]), "r"((a)[1]), "r"((a)[2]), "r"((a)[3]), "r"(b0v), "r"(b1v))

__device__ __forceinline__ void split_bf16(float v, __nv_bfloat16& hi, __nv_bfloat16& lo) {
    hi = __float2bfloat16(v);
    lo = __float2bfloat16(v - __bfloat162float(hi));
}
__device__ __forceinline__ uint32_t pack_bf2(float a, float b) {
    __nv_bfloat162 t = __halves2bfloat162(__float2bfloat16(a), __float2bfloat16(b));
    return *(uint32_t*)&t;
}
__device__ __forceinline__ float gelu_exact(float x) {
    return 0.5f * x * (1.0f + erff(x * 0.70710678118654752f));
}

// ================= weight conversion (coalesced transposes) =================
// W[K][N] fp32 -> O[N][K] split bf16, 32x32 smem tiles.
__global__ void tcvt_t(const float* __restrict__ W, __nv_bfloat16* __restrict__ Ohi,
                       __nv_bfloat16* __restrict__ Olo, int K, int N)
{
    __shared__ float t[32][33];
    int n0 = blockIdx.x * 32, k0 = blockIdx.y * 32;
    int tx = threadIdx.x, ty = threadIdx.y;
    #pragma unroll
    for (int j = 0; j < 4; j++)
        t[ty + 8 * j][tx] = W[(size_t)(k0 + ty + 8 * j) * N + n0 + tx];
    __syncthreads();
    #pragma unroll
    for (int j = 0; j < 4; j++) {
        int n = n0 + ty + 8 * j;
        float v = t[tx][ty + 8 * j];
        __nv_bfloat16 hi, lo; split_bf16(v, hi, lo);
        Ohi[(size_t)n * K + k0 + tx] = hi;
        Olo[(size_t)n * K + k0 + tx] = lo;
    }
}
// Wq/Wk/Wv [H][D][HD] -> g_Wqkv[(part*768+h*64+e)][d], transposed per (part,h)
__global__ void qkv_cvt_t(const float* __restrict__ Wq, const float* __restrict__ Wk,
                          const float* __restrict__ Wv)
{
    __shared__ float t[32][33];
    int d0 = blockIdx.x * 32, e0 = blockIdx.y * 32;
    int part = blockIdx.z / HH, h = blockIdx.z % HH;
    const float* W = (part == 0) ? Wq : (part == 1) ? Wk : Wv;
    int tx = threadIdx.x, ty = threadIdx.y;
    #pragma unroll
    for (int j = 0; j < 4; j++)
        t[ty + 8 * j][tx] = W[(size_t)(h * DD + d0 + ty + 8 * j) * HDD + e0 + tx];
    __syncthreads();
    #pragma unroll
    for (int j = 0; j < 4; j++) {
        int e = e0 + ty + 8 * j;
        int row = part * DD + h * HDD + e;
        float v = t[tx][ty + 8 * j];
        __nv_bfloat16 hi, lo; split_bf16(v, hi, lo);
        g_Wqkv_hi[(size_t)row * DD + d0 + tx] = hi;
        g_Wqkv_lo[(size_t)row * DD + d0 + tx] = lo;
    }
}
__global__ void qkv_bias(const float* __restrict__ bq, const float* __restrict__ bk,
                         const float* __restrict__ bv)
{
    int j = blockIdx.x * 256 + threadIdx.x;
    if (j >= NC) return;
    int part = j / DD, jj = j - part * DD;
    const float* bb = (part == 0) ? bq : (part == 1) ? bk : bv;
    g_bp[j] = bb[jj];
}

// ================= layer norm (writes split bf16) =================
__global__ void ln_kernel(const float* __restrict__ x, const float* __restrict__ g,
                          const float* __restrict__ b, __nv_bfloat16* __restrict__ yhi,
                          __nv_bfloat16* __restrict__ ylo)
{
    int row = blockIdx.x;
    int tid = threadIdx.x;
    const float* xr = x + (size_t)row * DD;
    float v0 = xr[tid], v1 = xr[tid + 256], v2 = xr[tid + 512];
    float s  = v0 + v1 + v2;
    float ss = v0 * v0 + v1 * v1 + v2 * v2;
    #pragma unroll
    for (int o = 16; o >= 1; o >>= 1) {
        s  += __shfl_xor_sync(0xffffffffu, s,  o);
        ss += __shfl_xor_sync(0xffffffffu, ss, o);
    }
    __shared__ float rs[8], rss[8];
    int w = tid >> 5, l = tid & 31;
    if (l == 0) { rs[w] = s; rss[w] = ss; }
    __syncthreads();
    float S = 0.f, S2 = 0.f;
    #pragma unroll
    for (int i = 0; i < 8; i++) { S += rs[i]; S2 += rss[i]; }
    float mu  = S  * (1.0f / DD);
    float var = S2 * (1.0f / DD) - mu * mu;
    float inv = rsqrtf(var + 1e-5f);
    #pragma unroll
    for (int q = 0; q < 3; q++) {
        int c = tid + q * 256;
        float v = (q == 0 ? v0 : q == 1 ? v1 : v2);
        float y = (v - mu) * inv * g[c] + b[c];
        __nv_bfloat16 hi, lo; split_bf16(y, hi, lo);
        yhi[(size_t)row * DD + c] = hi;
        ylo[(size_t)row * DD + c] = lo;
    }
}

// LN2 fused over 3 split-K partials + bias (a = sum + bo; y = LN(a) -> split)
__global__ void ln2_fuse(const float* __restrict__ bo, const float* __restrict__ g,
                         const float* __restrict__ b, __nv_bfloat16* __restrict__ yhi,
                         __nv_bfloat16* __restrict__ ylo)
{
    const size_t plane = (size_t)ROWS * DD;
    int row = blockIdx.x;
    int tid = threadIdx.x;
    const float* p = g_part + (size_t)row * DD;
    float v[3];
    #pragma unroll
    for (int q = 0; q < 3; q++) {
        int c = tid + q * 256;
        v[q] = p[c] + p[plane + c] + p[2 * plane + c] + bo[c];
    }
    float s  = v[0] + v[1] + v[2];
    float ss = v[0]*v[0] + v[1]*v[1] + v[2]*v[2];
    #pragma unroll
    for (int o = 16; o >= 1; o >>= 1) {
        s  += __shfl_xor_sync(0xffffffffu, s,  o);
        ss += __shfl_xor_sync(0xffffffffu, ss, o);
    }
    __shared__ float rs[8], rss[8];
    int w = tid >> 5, l = tid & 31;
    if (l == 0) { rs[w] = s; rss[w] = ss; }
    __syncthreads();
    float S = 0.f, S2 = 0.f;
    #pragma unroll
    for (int i = 0; i < 8; i++) { S += rs[i]; S2 += rss[i]; }
    float mu  = S  * (1.0f / DD);
    float var = S2 * (1.0f / DD) - mu * mu;
    float inv = rsqrtf(var + 1e-5f);
    #pragma unroll
    for (int q = 0; q < 3; q++) {
        int c = tid + q * 256;
        float y = (v[q] - mu) * inv * g[c] + b[c];
        __nv_bfloat16 hi, lo; split_bf16(y, hi, lo);
        yhi[(size_t)row * DD + c] = hi;
        ylo[(size_t)row * DD + c] = lo;
    }
}

// out = p0 + p1 + p2 + bias (FFN2 reduce)
__global__ void addbias3(const float* __restrict__ bias, float* __restrict__ out)
{
    const size_t plane = (size_t)ROWS * DD;
    size_t i4 = ((size_t)blockIdx.x * 256 + threadIdx.x) * 4;
    if (i4 >= plane) return;
    int c = (int)(i4 % DD);
    float4 a = *(const float4*)(g_part + i4);
    float4 b = *(const float4*)(g_part + plane + i4);
    float4 d = *(const float4*)(g_part + 2 * plane + i4);
    float4 bb = *(const float4*)(bias + c);
    float4 r;
    r.x = a.x + b.x + d.x + bb.x;
    r.y = a.y + b.y + d.y + bb.y;
    r.z = a.z + b.z + d.z + bb.z;
    r.w = a.w + b.w + d.w + bb.w;
    *(float4*)(out + i4) = r;
}

// ================ mma.sync GEMM: C[M,N] = A[M,K] @ Bt[N,K]^T ================
// PART=1: split-K partial (gridDim.z ways), fp32 out to g-plane z, no bias/act.
#define STAGE_B  32768
#define GEMM_SMEM (3*STAGE_B)

template<int ACT, int OSPLIT, int PART>
__global__ __launch_bounds__(256)
void tgemm(const __nv_bfloat16* __restrict__ Ahi, const __nv_bfloat16* __restrict__ Alo,
           const __nv_bfloat16* __restrict__ Bhi, const __nv_bfloat16* __restrict__ Blo,
           const float* __restrict__ bias,
           float* __restrict__ Cf, __nv_bfloat16* __restrict__ Chi,
           __nv_bfloat16* __restrict__ Clo, int N, int K)
{
    extern __shared__ char smem[];
    uint32_t ST = smem_u32(smem);
    int tid = threadIdx.x;
    int lane = tid & 31, wid = tid >> 5;
    int wr = wid & 3, wc = wid >> 2;          // warp grid 4 x 2
    int m0 = blockIdx.y * 128;
    int n0 = blockIdx.x * 128;
    int KH = PART ? (K / (int)gridDim.z) : K;
    int koff = PART ? ((int)blockIdx.z * KH) : 0;
    int nc = KH >> 5;                          // K chunks of 32

    const __nv_bfloat16* Abase_h = Ahi + (size_t)m0 * K + koff;
    const __nv_bfloat16* Abase_l = Alo + (size_t)m0 * K + koff;
    const __nv_bfloat16* Bbase_h = Bhi + (size_t)n0 * K + koff;
    const __nv_bfloat16* Bbase_l = Blo + (size_t)n0 * K + koff;

    auto load_chunk = [&](int c, int p) {
        uint32_t base = ST + p * STAGE_B;
        const __nv_bfloat16* ah = Abase_h + c * 32;
        const __nv_bfloat16* al = Abase_l + c * 32;
        const __nv_bfloat16* bh = Bbase_h + c * 32;
        const __nv_bfloat16* bl = Bbase_l + c * 32;
        #pragma unroll
        for (int j = 0; j < 2; j++) {
            int id = tid + 256 * j;            // 0..511 : 128 rows x 4 chunks
            int r = id >> 2, cc = id & 3;
            uint32_t off = (uint32_t)(r * 64 + ((cc ^ ((r >> 1) & 3)) << 4));
            const size_t go = (size_t)r * K + cc * 8;
            CP16(base +         off, ah + go);
            CP16(base +  8192 + off, al + go);
            CP16(base + 16384 + off, bh + go);
            CP16(base + 24576 + off, bl + go);
        }
    };

    float acc[2][8][4];
    #pragma unroll
    for (int s = 0; s < 2; s++)
        #pragma unroll
        for (int t = 0; t < 8; t++)
            #pragma unroll
            for (int q = 0; q < 4; q++) acc[s][t][q] = 0.f;

    load_chunk(0, 0); CP_COMMIT();
    load_chunk(1, 1); CP_COMMIT();
    load_chunk(2, 2); CP_COMMIT();

    int arow = wr * 32 + (lane & 15);
    int brow = wc * 64 + (lane & 15);
    int khalf = lane >> 4;

    for (int c = 0; c < nc; c++) {
        CP_WAIT(2);
        __syncthreads();
        uint32_t base = ST + (c % 3) * STAGE_B;
        uint32_t Ah = base, Al = base + 8192, Bh = base + 16384, Bl = base + 24576;
        #pragma unroll
        for (int ks = 0; ks < 2; ks++) {
            uint32_t ahf[2][4], alf[2][4];
            #pragma unroll
            for (int sub = 0; sub < 2; sub++) {
                int r = arow + sub * 16;
                int kc = ks * 2 + khalf;
                uint32_t off = (uint32_t)(r * 64 + ((kc ^ ((r >> 1) & 3)) << 4));
                LDM4(ahf[sub], Ah + off);
                LDM4(alf[sub], Al + off);
            }
            #pragma unroll
            for (int nh = 0; nh < 4; nh++) {
                int n = brow + nh * 16;
                int kc = ks * 2 + khalf;
                uint32_t off = (uint32_t)(n * 64 + ((kc ^ ((n >> 1) & 3)) << 4));
                uint32_t bhf[4], blf[4];
                LDM4(bhf, Bh + off);
                LDM4(blf, Bl + off);
                #pragma unroll
                for (int sub = 0; sub < 2; sub++) {
                    #pragma unroll
                    for (int nt = 0; nt < 2; nt++) {
                        float* d = acc[sub][nh * 2 + nt];
                        MMA16816(d, ahf[sub], bhf[nt], bhf[nt + 2]);
                        MMA16816(d, ahf[sub], blf[nt], blf[nt + 2]);
                        MMA16816(d, alf[sub], bhf[nt], bhf[nt + 2]);
                    }
                }
            }
        }
        __syncthreads();
        if (c + 3 < nc) load_chunk(c + 3, c % 3);
        CP_COMMIT();
    }

    // ---------------- epilogue ----------------
    float* Cpart = PART ? (Cf + (size_t)blockIdx.z * ROWS * N) : Cf;
    int g = lane >> 2, t = lane & 3;
    #pragma unroll
    for (int sub = 0; sub < 2; sub++) {
        #pragma unroll
        for (int nt8 = 0; nt8 < 8; nt8++) {
            int col = n0 + wc * 64 + nt8 * 8 + t * 2;
            float b0 = PART ? 0.f : bias[col];
            float b1 = PART ? 0.f : bias[col + 1];
            #pragma unroll
            for (int half = 0; half < 2; half++) {
                int row = m0 + wr * 32 + sub * 16 + g + half * 8;
                float v0 = acc[sub][nt8][half * 2 + 0] + b0;
                float v1 = acc[sub][nt8][half * 2 + 1] + b1;
                if (ACT) { v0 = gelu_exact(v0); v1 = gelu_exact(v1); }
                if (OSPLIT) {
                    __nv_bfloat16 h0, l0, h1, l1;
                    split_bf16(v0, h0, l0); split_bf16(v1, h1, l1);
                    *(__nv_bfloat162*)(Chi + (size_t)row * N + col) = __halves2bfloat162(h0, h1);
                    *(__nv_bfloat162*)(Clo + (size_t)row * N + col) = __halves2bfloat162(l0, l1);
                } else {
                    float2 fv; fv.x = v0; fv.y = v1;
                    *(float2*)(Cpart + (size_t)row * N + col) = fv;
                }
            }
        }
    }
}

// ============ tensor-core flash attention (bf16 split, 64x64 tiles) =========
#define ATT_STAGE 32768
#define ATT_SMEM  (16384 + 2*ATT_STAGE)

__device__ __forceinline__ uint32_t aoff(int r, int c) {
    return (uint32_t)((r << 7) + (((c ^ (r & 7)) & 7) << 4));
}

__global__ __launch_bounds__(128)
void attn_tc(const __nv_bfloat16* __restrict__ qh, const __nv_bfloat16* __restrict__ ql,
             __nv_bfloat16* __restrict__ ohi, __nv_bfloat16* __restrict__ olo)
{
    extern __shared__ char sm[];
    uint32_t S0 = smem_u32(sm);
    const uint32_t Qh = S0, Ql = S0 + 8192;
    int tid = threadIdx.x, lane = tid & 31, wid = tid >> 5;
    int bh = blockIdx.y, b = bh / HH, h = bh - b * HH;
    int q0 = blockIdx.x * 64;
    size_t rowbase = (size_t)b * SS * NC + h * 64;

    {
        const __nv_bfloat16* qph = qh + rowbase + (size_t)q0 * NC;
        const __nv_bfloat16* qpl = ql + rowbase + (size_t)q0 * NC;
        #pragma unroll
        for (int j = 0; j < 4; j++) {
            int id = tid + 128 * j; int r = id >> 3, c = id & 7;
            size_t go = (size_t)r * NC + c * 8;
            CP16(Qh + aoff(r, c), qph + go);
            CP16(Ql + aoff(r, c), qpl + go);
        }
        CP_COMMIT();
    }
    auto load_kv = [&](int kt, int p) {
        uint32_t base = S0 + 16384 + p * ATT_STAGE;
        size_t kb = rowbase + (size_t)(kt * 64) * NC + 768;
        size_t vb = kb + 768;
        #pragma unroll
        for (int j = 0; j < 4; j++) {
            int id = tid + 128 * j; int r = id >> 3, c = id & 7;
            uint32_t o_ = aoff(r, c);
            size_t go = (size_t)r * NC + c * 8;
            CP16(base +         o_, qh + kb + go);
            CP16(base +  8192 + o_, ql + kb + go);
            CP16(base + 16384 + o_, qh + vb + go);
            CP16(base + 24576 + o_, ql + vb + go);
        }
        CP_COMMIT();
    };
    load_kv(0, 0);
    load_kv(1, 1);

    float o[8][4];
    #pragma unroll
    for (int i = 0; i < 8; i++)
        #pragma unroll
        for (int q = 0; q < 4; q++) o[i][q] = 0.f;
    float m0r = -1e30f, m1r = -1e30f, l0r = 0.f, l1r = 0.f;
    int g = lane >> 2, t = lane & 3;
    int arow = wid * 16 + (lane & 15);
    int khalf = lane >> 4;

    for (int kt = 0; kt < SS / 64; kt++) {
        int p = kt & 1;
        CP_WAIT(1);
        __syncthreads();
        uint32_t base = S0 + 16384 + p * ATT_STAGE;
        uint32_t Kh = base, Kl = base + 8192, Vh = base + 16384, Vl = base + 24576;

        float s[8][4];
        #pragma unroll
        for (int i = 0; i < 8; i++)
            #pragma unroll
            for (int q = 0; q < 4; q++) s[i][q] = 0.f;
        #pragma unroll
        for (int ks = 0; ks < 4; ks++) {
            uint32_t qah[4], qal[4];
            uint32_t ao = aoff(arow, ks * 2 + khalf);
            LDM4(qah, Qh + ao);
            LDM4(qal, Ql + ao);
            #pragma unroll
            for (int np = 0; np < 4; np++) {
                uint32_t bo = aoff(np * 16 + (lane & 15), ks * 2 + khalf);
                uint32_t kbh[4], kbl[4];
                LDM4(kbh, Kh + bo);
                LDM4(kbl, Kl + bo);
                #pragma unroll
                for (int half = 0; half < 2; half++) {
                    float* d = s[np * 2 + half];
                    MMA16816(d, qah, kbh[half], kbh[half + 2]);
                    MMA16816(d, qah, kbl[half], kbl[half + 2]);
                    MMA16816(d, qal, kbh[half], kbh[half + 2]);
                }
            }
        }
        float mn0 = m0r, mn1 = m1r;
        #pragma unroll
        for (int nb = 0; nb < 8; nb++) {
            s[nb][0] *= 0.125f; s[nb][1] *= 0.125f;
            s[nb][2] *= 0.125f; s[nb][3] *= 0.125f;
            mn0 = fmaxf(mn0, fmaxf(s[nb][0], s[nb][1]));
            mn1 = fmaxf(mn1, fmaxf(s[nb][2], s[nb][3]));
        }
        mn0 = fmaxf(mn0, __shfl_xor_sync(0xffffffffu, mn0, 1));
        mn0 = fmaxf(mn0, __shfl_xor_sync(0xffffffffu, mn0, 2));
        mn1 = fmaxf(mn1, __shfl_xor_sync(0xffffffffu, mn1, 1));
        mn1 = fmaxf(mn1, __shfl_xor_sync(0xffffffffu, mn1, 2));
        float al0 = __expf(m0r - mn0), al1 = __expf(m1r - mn1);
        m0r = mn0; m1r = mn1;
        float sum0 = 0.f, sum1 = 0.f;
        uint32_t ph[4][4], pl[4][4];
        #pragma unroll
        for (int kg = 0; kg < 4; kg++) {
            #pragma unroll
            for (int half = 0; half < 2; half++) {
                int nb = kg * 2 + half;
                float p0 = __expf(s[nb][0] - mn0), p1 = __expf(s[nb][1] - mn0);
                float p2 = __expf(s[nb][2] - mn1), p3 = __expf(s[nb][3] - mn1);
                sum0 += p0 + p1; sum1 += p2 + p3;
                float h0 = __bfloat162float(__float2bfloat16(p0));
                float h1 = __bfloat162float(__float2bfloat16(p1));
                float h2 = __bfloat162float(__float2bfloat16(p2));
                float h3 = __bfloat162float(__float2bfloat16(p3));
                ph[kg][half * 2 + 0] = pack_bf2(p0, p1);
                ph[kg][half * 2 + 1] = pack_bf2(p2, p3);
                pl[kg][half * 2 + 0] = pack_bf2(p0 - h0, p1 - h1);
                pl[kg][half * 2 + 1] = pack_bf2(p2 - h2, p3 - h3);
            }
        }
        l0r = l0r * al0 + sum0;
        l1r = l1r * al1 + sum1;
        #pragma unroll
        for (int nb = 0; nb < 8; nb++) {
            o[nb][0] *= al0; o[nb][1] *= al0;
            o[nb][2] *= al1; o[nb][3] *= al1;
        }
        #pragma unroll
        for (int kg = 0; kg < 4; kg++) {
            #pragma unroll
            for (int ep = 0; ep < 4; ep++) {
                uint32_t vo = aoff(kg * 16 + (lane & 15), ep * 2 + khalf);
                uint32_t vbh[4], vbl[4];
                LDM4T(vbh, Vh + vo);
                LDM4T(vbl, Vl + vo);
                #pragma unroll
                for (int half = 0; half < 2; half++) {
                    float* d = o[ep * 2 + half];
                    MMA16816(d, ph[kg], vbh[half * 2], vbh[half * 2 + 1]);
                    MMA16816(d, ph[kg], vbl[half * 2], vbl[half * 2 + 1]);
                    MMA16816(d, pl[kg], vbh[half * 2], vbh[half * 2 + 1]);
                }
            }
        }
        __syncthreads();
        if (kt + 2 < SS / 64) load_kv(kt + 2, p);
    }
    l0r += __shfl_xor_sync(0xffffffffu, l0r, 1);
    l0r += __shfl_xor_sync(0xffffffffu, l0r, 2);
    l1r += __shfl_xor_sync(0xffffffffu, l1r, 1);
    l1r += __shfl_xor_sync(0xffffffffu, l1r, 2);
    float inv0 = 1.f / l0r, inv1 = 1.f / l1r;
    int r0 = q0 + wid * 16 + g, r1 = r0 + 8;
    #pragma unroll
    for (int eb = 0; eb < 8; eb++) {
        int col = h * 64 + eb * 8 + t * 2;
        size_t o0 = (size_t)(b * SS + r0) * DD + col;
        size_t o1 = (size_t)(b * SS + r1) * DD + col;
        float v00 = o[eb][0] * inv0, v01 = o[eb][1] * inv0;
        float v10 = o[eb][2] * inv1, v11 = o[eb][3] * inv1;
        __nv_bfloat16 h0, l0, h1, l1, h2, l2, h3, l3;
        split_bf16(v00, h0, l0); split_bf16(v01, h1, l1);
        split_bf16(v10, h2, l2); split_bf16(v11, h3, l3);
        *(__nv_bfloat162*)(ohi + o0) = __halves2bfloat162(h0, h1);
        *(__nv_bfloat162*)(olo + o0) = __halves2bfloat162(l0, l1);
        *(__nv_bfloat162*)(ohi + o1) = __halves2bfloat162(h2, h3);
        *(__nv_bfloat162*)(olo + o1) = __halves2bfloat162(l2, l3);
    }
}

// ================= launch =================
extern "C" void kernel_launch(void* const* d_in, const int* in_sizes, int n_in,
                              void* d_out, int out_size)
{
    const float* x   = (const float*)d_in[0];
    const float* Wq  = (const float*)d_in[1];
    const float* bq  = (const float*)d_in[2];
    const float* Wk  = (const float*)d_in[3];
    const float* bk  = (const float*)d_in[4];
    const float* Wv  = (const float*)d_in[5];
    const float* bv  = (const float*)d_in[6];
    const float* Wo  = (const float*)d_in[7];
    const float* bo  = (const float*)d_in[8];
    const float* W1  = (const float*)d_in[9];
    const float* b1  = (const float*)d_in[10];
    const float* W2  = (const float*)d_in[11];
    const float* b2  = (const float*)d_in[12];
    const float* g1  = (const float*)d_in[13];
    const float* be1 = (const float*)d_in[14];
    const float* g2  = (const float*)d_in[15];
    const float* be2 = (const float*)d_in[16];
    float* out = (float*)d_out;

    void *ppart, *pbp, *phh, *phl, *pqh, *pql, *poh, *pol, *pfh, *pfl;
    void *pWoh, *pWol, *pW1h, *pW1l, *pW2h, *pW2l, *pWqh, *pWql;
    cudaGetSymbolAddress(&ppart, g_part);
    cudaGetSymbolAddress(&pbp,  g_bp);
    cudaGetSymbolAddress(&phh,  g_h_hi);  cudaGetSymbolAddress(&phl, g_h_lo);
    cudaGetSymbolAddress(&pqh,  g_qkvh);  cudaGetSymbolAddress(&pql, g_qkvl);
    cudaGetSymbolAddress(&poh,  g_o_hi);  cudaGetSymbolAddress(&pol, g_o_lo);
    cudaGetSymbolAddress(&pfh,  g_f_hi);  cudaGetSymbolAddress(&pfl, g_f_lo);
    cudaGetSymbolAddress(&pWqh, g_Wqkv_hi); cudaGetSymbolAddress(&pWql, g_Wqkv_lo);
    cudaGetSymbolAddress(&pWoh, g_Wo_hi);   cudaGetSymbolAddress(&pWol, g_Wo_lo);
    cudaGetSymbolAddress(&pW1h, g_W1_hi);   cudaGetSymbolAddress(&pW1l, g_W1_lo);
    cudaGetSymbolAddress(&pW2h, g_W2_hi);   cudaGetSymbolAddress(&pW2l, g_W2_lo);
    float* part = (float*)ppart;
    float* bp   = (float*)pbp;
    __nv_bfloat16* hh = (__nv_bfloat16*)phh, *hl = (__nv_bfloat16*)phl;
    __nv_bfloat16* qvh = (__nv_bfloat16*)pqh, *qvl = (__nv_bfloat16*)pql;
    __nv_bfloat16* oh = (__nv_bfloat16*)poh, *ol = (__nv_bfloat16*)pol;
    __nv_bfloat16* fh = (__nv_bfloat16*)pfh, *fl = (__nv_bfloat16*)pfl;
    __nv_bfloat16* Wqh = (__nv_bfloat16*)pWqh, *Wql = (__nv_bfloat16*)pWql;
    __nv_bfloat16* Woh = (__nv_bfloat16*)pWoh, *Wol = (__nv_bfloat16*)pWol;
    __nv_bfloat16* W1h = (__nv_bfloat16*)pW1h, *W1l = (__nv_bfloat16*)pW1l;
    __nv_bfloat16* W2h = (__nv_bfloat16*)pW2h, *W2l = (__nv_bfloat16*)pW2l;

    cudaFuncSetAttribute(tgemm<0,1,0>, cudaFuncAttributeMaxDynamicSharedMemorySize, GEMM_SMEM);
    cudaFuncSetAttribute(tgemm<0,0,1>, cudaFuncAttributeMaxDynamicSharedMemorySize, GEMM_SMEM);
    cudaFuncSetAttribute(tgemm<1,1,0>, cudaFuncAttributeMaxDynamicSharedMemorySize, GEMM_SMEM);
    cudaFuncSetAttribute(attn_tc,      cudaFuncAttributeMaxDynamicSharedMemorySize, ATT_SMEM);

    // weight prep (coalesced transposes)
    qkv_cvt_t<<<dim3(DD/32, HDD/32, 3*HH), dim3(32,8)>>>(Wq, Wk, Wv);
    qkv_bias<<<(NC + 255)/256, 256>>>(bq, bk, bv);
    tcvt_t<<<dim3(DD/32, DD/32),  dim3(32,8)>>>(Wo, Woh, Wol, DD, DD);
    tcvt_t<<<dim3(FF/32, DD/32),  dim3(32,8)>>>(W1, W1h, W1l, DD, FF);
    tcvt_t<<<dim3(DD/32, FF/32),  dim3(32,8)>>>(W2, W2h, W2l, FF, DD);
    // LN1 -> split
    ln_kernel<<<ROWS, 256>>>(x, g1, be1, hh, hl);
    // QKV projection -> split bf16 qkv
    tgemm<0,1,0><<<dim3(NC/128, ROWS/128), 256, GEMM_SMEM>>>(
        hh, hl, Wqh, Wql, bp, nullptr, qvh, qvl, NC, DD);
    // tensor-core flash attention -> split bf16 o
    attn_tc<<<dim3(SS/64, BB*HH), 128, ATT_SMEM>>>(qvh, qvl, oh, ol);
    // output projection: split-K=3 partials
    tgemm<0,0,1><<<dim3(DD/128, ROWS/128, 3), 256, GEMM_SMEM>>>(
        oh, ol, Woh, Wol, nullptr, part, nullptr, nullptr, DD, DD);
    // fused reduce + bias + LN2 -> split
    ln2_fuse<<<ROWS, 256>>>(bo, g2, be2, hh, hl);
    // FFN up + GELU -> split
    tgemm<1,1,0><<<dim3(FF/128, ROWS/128), 256, GEMM_SMEM>>>(
        hh, hl, W1h, W1l, b1, nullptr, fh, fl, FF, DD);
    // FFN down: split-K=3 partials
    tgemm<0,0,1><<<dim3(DD/128, ROWS/128, 3), 256, GEMM_SMEM>>>(
        fh, fl, W2h, W2l, nullptr, part, nullptr, nullptr, DD, FF);
    // reduce + bias -> output
    addbias3<<<(ROWS*DD/4 + 255)/256, 256>>>(b2, out);
}

// round 11
// speedup vs baseline: 2.7289x; 1.0919x over previous
#include <cuda_runtime.h>
#include <cuda_bf16.h>
#include <math.h>
#include <stdint.h>

// Problem constants
#define BB   4
#define SS   2048
#define DD   768
#define HH   12
#define HDD  64
#define FF   3072
#define ROWS (BB*SS)   // 8192
#define NC   2304      // 3*DD packed qkv cols

// ---------------- scratch (device globals; no runtime allocation) ----------
__device__ float g_part[3*(size_t)ROWS*DD];      // split-K fp32 partials (3 planes)
__device__ float g_bp [NC];                      // packed QKV bias
__device__ __align__(256) __nv_bfloat16 g_h_hi[ROWS*DD], g_h_lo[ROWS*DD];
__device__ __align__(256) __nv_bfloat16 g_qkvh[ROWS*NC], g_qkvl[ROWS*NC];   // split qkv
__device__ __align__(256) __nv_bfloat16 g_o_hi[ROWS*DD], g_o_lo[ROWS*DD];
__device__ __align__(256) __nv_bfloat16 g_f_hi[ROWS*FF], g_f_lo[ROWS*FF];
__device__ __align__(256) __nv_bfloat16 g_Wqkv_hi[NC*DD], g_Wqkv_lo[NC*DD]; // [2304][768]
__device__ __align__(256) __nv_bfloat16 g_Wo_hi[DD*DD],  g_Wo_lo[DD*DD];    // [768][768]
__device__ __align__(256) __nv_bfloat16 g_W1_hi[FF*DD],  g_W1_lo[FF*DD];    // [3072][768]
__device__ __align__(256) __nv_bfloat16 g_W2_hi[DD*FF],  g_W2_lo[DD*FF];    // [768][3072]

// ================= PTX helpers (baseline ISA only: sm_80-class) =============
__device__ __forceinline__ uint32_t smem_u32(const void* p) {
    uint32_t a;
    asm("{ .reg .u64 t; cvta.to.shared.u64 t, %1; cvt.u32.u64 %0, t; }" : "=r"(a) : "l"(p));
    return a;
}
#define CP16(dst, src) asm volatile("cp.async.cg.shared.global [%0], [%1], 16;" :: "r"(dst), "l"(src))
#define CP_COMMIT()    asm volatile("cp.async.commit_group;" ::: "memory")
#define CP_WAIT(n)     asm volatile("cp.async.wait_group %0;" :: "n"(n) : "memory")

#define LDM4(r, addr) \
    asm volatile("ldmatrix.sync.aligned.m8n8.x4.shared.b16 {%0,%1,%2,%3}, [%4];" \
        : "=r"((r)[0]), "=r"((r)[1]), "=r"((r)[2]), "=r"((r)[3]) : "r"(addr))
#define LDM4T(r, addr) \
    asm volatile("ldmatrix.sync.aligned.m8n8.x4.trans.shared.b16 {%0,%1,%2,%3}, [%4];" \
        : "=r"((r)[0]), "=r"((r)[1]), "=r"((r)[2]), "=r"((r)[3]) : "r"(addr))

#define MMA16816(d, a, b0v, b1v) \
    asm volatile("mma.sync.aligned.m16n8k16.row.col.f32.bf16.bf16.f32 " \
        "{%0,%1,%2,%3},{%4,%5,%6,%7},{%8,%9},{%0,%1,%2,%3};" \
        : "+f"((d)[0]), "+f"((d)[1]), "+f"((d)[2]), "+f"((d)[3]) \
        : "r"((a)[0]), "r"((a)[1]), "r"((a)[2]), "r"((a)[3]), "r"(b0v), "r"(b1v))

__device__ __forceinline__ void split_bf16(float v, __nv_bfloat16& hi, __nv_bfloat16& lo) {
    hi = __float2bfloat16(v);
    lo = __float2bfloat16(v - __bfloat162float(hi));
}
__device__ __forceinline__ uint32_t pack_bf2(float a, float b) {
    __nv_bfloat162 t = __halves2bfloat162(__float2bfloat16(a), __float2bfloat16(b));
    return *(uint32_t*)&t;
}
__device__ __forceinline__ float gelu_exact(float x) {
    return 0.5f * x * (1.0f + erff(x * 0.70710678118654752f));
}

// ================= weight conversion (coalesced transposes) =================
// W[K][N] fp32 -> O[N][K] split bf16, 32x32 smem tiles.
__global__ void tcvt_t(const float* __restrict__ W, __nv_bfloat16* __restrict__ Ohi,
                       __nv_bfloat16* __restrict__ Olo, int K, int N)
{
    __shared__ float t[32][33];
    int n0 = blockIdx.x * 32, k0 = blockIdx.y * 32;
    int tx = threadIdx.x, ty = threadIdx.y;
    #pragma unroll
    for (int j = 0; j < 4; j++)
        t[ty + 8 * j][tx] = W[(size_t)(k0 + ty + 8 * j) * N + n0 + tx];
    __syncthreads();
    #pragma unroll
    for (int j = 0; j < 4; j++) {
        int n = n0 + ty + 8 * j;
        float v = t[tx][ty + 8 * j];
        __nv_bfloat16 hi, lo; split_bf16(v, hi, lo);
        Ohi[(size_t)n * K + k0 + tx] = hi;
        Olo[(size_t)n * K + k0 + tx] = lo;
    }
}
// Wq/Wk/Wv [H][D][HD] -> g_Wqkv[(part*768+h*64+e)][d], transposed per (part,h)
__global__ void qkv_cvt_t(const float* __restrict__ Wq, const float* __restrict__ Wk,
                          const float* __restrict__ Wv)
{
    __shared__ float t[32][33];
    int d0 = blockIdx.x * 32, e0 = blockIdx.y * 32;
    int part = blockIdx.z / HH, h = blockIdx.z % HH;
    const float* W = (part == 0) ? Wq : (part == 1) ? Wk : Wv;
    int tx = threadIdx.x, ty = threadIdx.y;
    #pragma unroll
    for (int j = 0; j < 4; j++)
        t[ty + 8 * j][tx] = W[(size_t)(h * DD + d0 + ty + 8 * j) * HDD + e0 + tx];
    __syncthreads();
    #pragma unroll
    for (int j = 0; j < 4; j++) {
        int e = e0 + ty + 8 * j;
        int row = part * DD + h * HDD + e;
        float v = t[tx][ty + 8 * j];
        __nv_bfloat16 hi, lo; split_bf16(v, hi, lo);
        g_Wqkv_hi[(size_t)row * DD + d0 + tx] = hi;
        g_Wqkv_lo[(size_t)row * DD + d0 + tx] = lo;
    }
}
__global__ void qkv_bias(const float* __restrict__ bq, const float* __restrict__ bk,
                         const float* __restrict__ bv)
{
    int j = blockIdx.x * 256 + threadIdx.x;
    if (j >= NC) return;
    int part = j / DD, jj = j - part * DD;
    const float* bb = (part == 0) ? bq : (part == 1) ? bk : bv;
    g_bp[j] = bb[jj];
}

// ================= layer norm (writes split bf16) =================
__global__ void ln_kernel(const float* __restrict__ x, const float* __restrict__ g,
                          const float* __restrict__ b, __nv_bfloat16* __restrict__ yhi,
                          __nv_bfloat16* __restrict__ ylo)
{
    int row = blockIdx.x;
    int tid = threadIdx.x;
    const float* xr = x + (size_t)row * DD;
    float v0 = xr[tid], v1 = xr[tid + 256], v2 = xr[tid + 512];
    float s  = v0 + v1 + v2;
    float ss = v0 * v0 + v1 * v1 + v2 * v2;
    #pragma unroll
    for (int o = 16; o >= 1; o >>= 1) {
        s  += __shfl_xor_sync(0xffffffffu, s,  o);
        ss += __shfl_xor_sync(0xffffffffu, ss, o);
    }
    __shared__ float rs[8], rss[8];
    int w = tid >> 5, l = tid & 31;
    if (l == 0) { rs[w] = s; rss[w] = ss; }
    __syncthreads();
    float S = 0.f, S2 = 0.f;
    #pragma unroll
    for (int i = 0; i < 8; i++) { S += rs[i]; S2 += rss[i]; }
    float mu  = S  * (1.0f / DD);
    float var = S2 * (1.0f / DD) - mu * mu;
    float inv = rsqrtf(var + 1e-5f);
    #pragma unroll
    for (int q = 0; q < 3; q++) {
        int c = tid + q * 256;
        float v = (q == 0 ? v0 : q == 1 ? v1 : v2);
        float y = (v - mu) * inv * g[c] + b[c];
        __nv_bfloat16 hi, lo; split_bf16(y, hi, lo);
        yhi[(size_t)row * DD + c] = hi;
        ylo[(size_t)row * DD + c] = lo;
    }
}

// LN2 fused over 3 split-K partials + bias (a = sum + bo; y = LN(a) -> split)
__global__ void ln2_fuse(const float* __restrict__ bo, const float* __restrict__ g,
                         const float* __restrict__ b, __nv_bfloat16* __restrict__ yhi,
                         __nv_bfloat16* __restrict__ ylo)
{
    const size_t plane = (size_t)ROWS * DD;
    int row = blockIdx.x;
    int tid = threadIdx.x;
    const float* p = g_part + (size_t)row * DD;
    float v[3];
    #pragma unroll
    for (int q = 0; q < 3; q++) {
        int c = tid + q * 256;
        v[q] = p[c] + p[plane + c] + p[2 * plane + c] + bo[c];
    }
    float s  = v[0] + v[1] + v[2];
    float ss = v[0]*v[0] + v[1]*v[1] + v[2]*v[2];
    #pragma unroll
    for (int o = 16; o >= 1; o >>= 1) {
        s  += __shfl_xor_sync(0xffffffffu, s,  o);
        ss += __shfl_xor_sync(0xffffffffu, ss, o);
    }
    __shared__ float rs[8], rss[8];
    int w = tid >> 5, l = tid & 31;
    if (l == 0) { rs[w] = s; rss[w] = ss; }
    __syncthreads();
    float S = 0.f, S2 = 0.f;
    #pragma unroll
    for (int i = 0; i < 8; i++) { S += rs[i]; S2 += rss[i]; }
    float mu  = S  * (1.0f / DD);
    float var = S2 * (1.0f / DD) - mu * mu;
    float inv = rsqrtf(var + 1e-5f);
    #pragma unroll
    for (int q = 0; q < 3; q++) {
        int c = tid + q * 256;
        float y = (v[q] - mu) * inv * g[c] + b[c];
        __nv_bfloat16 hi, lo; split_bf16(y, hi, lo);
        yhi[(size_t)row * DD + c] = hi;
        ylo[(size_t)row * DD + c] = lo;
    }
}

// out = p0 + p1 + p2 + bias (FFN2 reduce)
__global__ void addbias3(const float* __restrict__ bias, float* __restrict__ out)
{
    const size_t plane = (size_t)ROWS * DD;
    size_t i4 = ((size_t)blockIdx.x * 256 + threadIdx.x) * 4;
    if (i4 >= plane) return;
    int c = (int)(i4 % DD);
    float4 a = *(const float4*)(g_part + i4);
    float4 b = *(const float4*)(g_part + plane + i4);
    float4 d = *(const float4*)(g_part + 2 * plane + i4);
    float4 bb = *(const float4*)(bias + c);
    float4 r;
    r.x = a.x + b.x + d.x + bb.x;
    r.y = a.y + b.y + d.y + bb.y;
    r.z = a.z + b.z + d.z + bb.z;
    r.w = a.w + b.w + d.w + bb.w;
    *(float4*)(out + i4) = r;
}

// ================ mma.sync GEMM: C[M,N] = A[M,K] @ Bt[N,K]^T ================
// PART=1: split-K partial (gridDim.z ways), fp32 out to g-plane z, no bias/act.
// __launch_bounds__(256, 2): cap regs at 128 so 2 CTAs/SM co-reside (smem
// 96KB*2 = 192KB fits) -- one CTA's MMA stream hides the other's sync stalls.
#define STAGE_B  32768
#define GEMM_SMEM (3*STAGE_B)

template<int ACT, int OSPLIT, int PART>
__global__ __launch_bounds__(256, 2)
void tgemm(const __nv_bfloat16* __restrict__ Ahi, const __nv_bfloat16* __restrict__ Alo,
           const __nv_bfloat16* __restrict__ Bhi, const __nv_bfloat16* __restrict__ Blo,
           const float* __restrict__ bias,
           float* __restrict__ Cf, __nv_bfloat16* __restrict__ Chi,
           __nv_bfloat16* __restrict__ Clo, int N, int K)
{
    extern __shared__ char smem[];
    uint32_t ST = smem_u32(smem);
    int tid = threadIdx.x;
    int lane = tid & 31, wid = tid >> 5;
    int wr = wid & 3, wc = wid >> 2;          // warp grid 4 x 2
    int m0 = blockIdx.y * 128;
    int n0 = blockIdx.x * 128;
    int KH = PART ? (K / (int)gridDim.z) : K;
    int koff = PART ? ((int)blockIdx.z * KH) : 0;
    int nc = KH >> 5;                          // K chunks of 32

    const __nv_bfloat16* Abase_h = Ahi + (size_t)m0 * K + koff;
    const __nv_bfloat16* Abase_l = Alo + (size_t)m0 * K + koff;
    const __nv_bfloat16* Bbase_h = Bhi + (size_t)n0 * K + koff;
    const __nv_bfloat16* Bbase_l = Blo + (size_t)n0 * K + koff;

    auto load_chunk = [&](int c, int p) {
        uint32_t base = ST + p * STAGE_B;
        const __nv_bfloat16* ah = Abase_h + c * 32;
        const __nv_bfloat16* al = Abase_l + c * 32;
        const __nv_bfloat16* bh = Bbase_h + c * 32;
        const __nv_bfloat16* bl = Bbase_l + c * 32;
        #pragma unroll
        for (int j = 0; j < 2; j++) {
            int id = tid + 256 * j;            // 0..511 : 128 rows x 4 chunks
            int r = id >> 2, cc = id & 3;
            uint32_t off = (uint32_t)(r * 64 + ((cc ^ ((r >> 1) & 3)) << 4));
            const size_t go = (size_t)r * K + cc * 8;
            CP16(base +         off, ah + go);
            CP16(base +  8192 + off, al + go);
            CP16(base + 16384 + off, bh + go);
            CP16(base + 24576 + off, bl + go);
        }
    };

    float acc[2][8][4];
    #pragma unroll
    for (int s = 0; s < 2; s++)
        #pragma unroll
        for (int t = 0; t < 8; t++)
            #pragma unroll
            for (int q = 0; q < 4; q++) acc[s][t][q] = 0.f;

    load_chunk(0, 0); CP_COMMIT();
    load_chunk(1, 1); CP_COMMIT();
    load_chunk(2, 2); CP_COMMIT();

    int arow = wr * 32 + (lane & 15);
    int brow = wc * 64 + (lane & 15);
    int khalf = lane >> 4;

    for (int c = 0; c < nc; c++) {
        CP_WAIT(2);
        __syncthreads();
        uint32_t base = ST + (c % 3) * STAGE_B;
        uint32_t Ah = base, Al = base + 8192, Bh = base + 16384, Bl = base + 24576;
        #pragma unroll
        for (int ks = 0; ks < 2; ks++) {
            uint32_t ahf[2][4], alf[2][4];
            #pragma unroll
            for (int sub = 0; sub < 2; sub++) {
                int r = arow + sub * 16;
                int kc = ks * 2 + khalf;
                uint32_t off = (uint32_t)(r * 64 + ((kc ^ ((r >> 1) & 3)) << 4));
                LDM4(ahf[sub], Ah + off);
                LDM4(alf[sub], Al + off);
            }
            #pragma unroll
            for (int nh = 0; nh < 4; nh++) {
                int n = brow + nh * 16;
                int kc = ks * 2 + khalf;
                uint32_t off = (uint32_t)(n * 64 + ((kc ^ ((n >> 1) & 3)) << 4));
                uint32_t bhf[4], blf[4];
                LDM4(bhf, Bh + off);
                LDM4(blf, Bl + off);
                #pragma unroll
                for (int sub = 0; sub < 2; sub++) {
                    #pragma unroll
                    for (int nt = 0; nt < 2; nt++) {
                        float* d = acc[sub][nh * 2 + nt];
                        MMA16816(d, ahf[sub], bhf[nt], bhf[nt + 2]);
                        MMA16816(d, ahf[sub], blf[nt], blf[nt + 2]);
                        MMA16816(d, alf[sub], bhf[nt], bhf[nt + 2]);
                    }
                }
            }
        }
        __syncthreads();
        if (c + 3 < nc) load_chunk(c + 3, c % 3);
        CP_COMMIT();
    }

    // ---------------- epilogue ----------------
    float* Cpart = PART ? (Cf + (size_t)blockIdx.z * ROWS * N) : Cf;
    int g = lane >> 2, t = lane & 3;
    #pragma unroll
    for (int sub = 0; sub < 2; sub++) {
        #pragma unroll
        for (int nt8 = 0; nt8 < 8; nt8++) {
            int col = n0 + wc * 64 + nt8 * 8 + t * 2;
            float b0 = PART ? 0.f : bias[col];
            float b1 = PART ? 0.f : bias[col + 1];
            #pragma unroll
            for (int half = 0; half < 2; half++) {
                int row = m0 + wr * 32 + sub * 16 + g + half * 8;
                float v0 = acc[sub][nt8][half * 2 + 0] + b0;
                float v1 = acc[sub][nt8][half * 2 + 1] + b1;
                if (ACT) { v0 = gelu_exact(v0); v1 = gelu_exact(v1); }
                if (OSPLIT) {
                    __nv_bfloat16 h0, l0, h1, l1;
                    split_bf16(v0, h0, l0); split_bf16(v1, h1, l1);
                    *(__nv_bfloat162*)(Chi + (size_t)row * N + col) = __halves2bfloat162(h0, h1);
                    *(__nv_bfloat162*)(Clo + (size_t)row * N + col) = __halves2bfloat162(l0, l1);
                } else {
                    float2 fv; fv.x = v0; fv.y = v1;
                    *(float2*)(Cpart + (size_t)row * N + col) = fv;
                }
            }
        }
    }
}

// ============ tensor-core flash attention (bf16 split, 64x64 tiles) =========
// 3-stage KV pipeline, loads issued BEFORE compute each iteration (stage
// (kt+2)%3 is the one iter kt-1 just finished reading). Uniform CP_COMMIT
// every iter keeps wait_group arithmetic exact on the tail (fixes the latent
// last-tile race of the 2-stage version). ATT_SMEM = 114688 -> exactly 2
// CTAs/SM.
#define ATT_STAGE 32768
#define ATT_SMEM  (16384 + 3*ATT_STAGE)

__device__ __forceinline__ uint32_t aoff(int r, int c) {
    return (uint32_t)((r << 7) + (((c ^ (r & 7)) & 7) << 4));
}

__global__ __launch_bounds__(128, 2)
void attn_tc(const __nv_bfloat16* __restrict__ qh, const __nv_bfloat16* __restrict__ ql,
             __nv_bfloat16* __restrict__ ohi, __nv_bfloat16* __restrict__ olo)
{
    extern __shared__ char sm[];
    uint32_t S0 = smem_u32(sm);
    const uint32_t Qh = S0, Ql = S0 + 8192;
    int tid = threadIdx.x, lane = tid & 31, wid = tid >> 5;
    int bh = blockIdx.y, b = bh / HH, h = bh - b * HH;
    int q0 = blockIdx.x * 64;
    size_t rowbase = (size_t)b * SS * NC + h * 64;
    const int NT = SS / 64;

    {
        const __nv_bfloat16* qph = qh + rowbase + (size_t)q0 * NC;
        const __nv_bfloat16* qpl = ql + rowbase + (size_t)q0 * NC;
        #pragma unroll
        for (int j = 0; j < 4; j++) {
            int id = tid + 128 * j; int r = id >> 3, c = id & 7;
            size_t go = (size_t)r * NC + c * 8;
            CP16(Qh + aoff(r, c), qph + go);
            CP16(Ql + aoff(r, c), qpl + go);
        }
        CP_COMMIT();
    }
    auto load_kv = [&](int kt, int p) {
        uint32_t base = S0 + 16384 + p * ATT_STAGE;
        size_t kb = rowbase + (size_t)(kt * 64) * NC + 768;
        size_t vb = kb + 768;
        #pragma unroll
        for (int j = 0; j < 4; j++) {
            int id = tid + 128 * j; int r = id >> 3, c = id & 7;
            uint32_t o_ = aoff(r, c);
            size_t go = (size_t)r * NC + c * 8;
            CP16(base +         o_, qh + kb + go);
            CP16(base +  8192 + o_, ql + kb + go);
            CP16(base + 16384 + o_, qh + vb + go);
            CP16(base + 24576 + o_, ql + vb + go);
        }
    };
    load_kv(0, 0); CP_COMMIT();
    load_kv(1, 1); CP_COMMIT();

    float o[8][4];
    #pragma unroll
    for (int i = 0; i < 8; i++)
        #pragma unroll
        for (int q = 0; q < 4; q++) o[i][q] = 0.f;
    float m0r = -1e30f, m1r = -1e30f, l0r = 0.f, l1r = 0.f;
    int g = lane >> 2, t = lane & 3;
    int arow = wid * 16 + (lane & 15);
    int khalf = lane >> 4;

    for (int kt = 0; kt < NT; kt++) {
        int p = kt % 3;
        CP_WAIT(1);                 // stage kt landed (1 newer group may be in flight)
        __syncthreads();            // all warps past iter kt-1 compute (stage (kt+2)%3 free)
        if (kt + 2 < NT) load_kv(kt + 2, (kt + 2) % 3);
        CP_COMMIT();                // empty when skipped: keeps group count uniform
        uint32_t base = S0 + 16384 + p * ATT_STAGE;
        uint32_t Kh = base, Kl = base + 8192, Vh = base + 16384, Vl = base + 24576;

        float s[8][4];
        #pragma unroll
        for (int i = 0; i < 8; i++)
            #pragma unroll
            for (int q = 0; q < 4; q++) s[i][q] = 0.f;
        #pragma unroll
        for (int ks = 0; ks < 4; ks++) {
            uint32_t qah[4], qal[4];
            uint32_t ao = aoff(arow, ks * 2 + khalf);
            LDM4(qah, Qh + ao);
            LDM4(qal, Ql + ao);
            #pragma unroll
            for (int np = 0; np < 4; np++) {
                uint32_t bo = aoff(np * 16 + (lane & 15), ks * 2 + khalf);
                uint32_t kbh[4], kbl[4];
                LDM4(kbh, Kh + bo);
                LDM4(kbl, Kl + bo);
                #pragma unroll
                for (int half = 0; half < 2; half++) {
                    float* d = s[np * 2 + half];
                    MMA16816(d, qah, kbh[half], kbh[half + 2]);
                    MMA16816(d, qah, kbl[half], kbl[half + 2]);
                    MMA16816(d, qal, kbh[half], kbh[half + 2]);
                }
            }
        }
        float mn0 = m0r, mn1 = m1r;
        #pragma unroll
        for (int nb = 0; nb < 8; nb++) {
            s[nb][0] *= 0.125f; s[nb][1] *= 0.125f;
            s[nb][2] *= 0.125f; s[nb][3] *= 0.125f;
            mn0 = fmaxf(mn0, fmaxf(s[nb][0], s[nb][1]));
            mn1 = fmaxf(mn1, fmaxf(s[nb][2], s[nb][3]));
        }
        mn0 = fmaxf(mn0, __shfl_xor_sync(0xffffffffu, mn0, 1));
        mn0 = fmaxf(mn0, __shfl_xor_sync(0xffffffffu, mn0, 2));
        mn1 = fmaxf(mn1, __shfl_xor_sync(0xffffffffu, mn1, 1));
        mn1 = fmaxf(mn1, __shfl_xor_sync(0xffffffffu, mn1, 2));
        float al0 = __expf(m0r - mn0), al1 = __expf(m1r - mn1);
        m0r = mn0; m1r = mn1;
        float sum0 = 0.f, sum1 = 0.f;
        uint32_t ph[4][4], pl[4][4];
        #pragma unroll
        for (int kg = 0; kg < 4; kg++) {
            #pragma unroll
            for (int half = 0; half < 2; half++) {
                int nb = kg * 2 + half;
                float p0 = __expf(s[nb][0] - mn0), p1 = __expf(s[nb][1] - mn0);
                float p2 = __expf(s[nb][2] - mn1), p3 = __expf(s[nb][3] - mn1);
                sum0 += p0 + p1; sum1 += p2 + p3;
                float h0 = __bfloat162float(__float2bfloat16(p0));
                float h1 = __bfloat162float(__float2bfloat16(p1));
                float h2 = __bfloat162float(__float2bfloat16(p2));
                float h3 = __bfloat162float(__float2bfloat16(p3));
                ph[kg][half * 2 + 0] = pack_bf2(p0, p1);
                ph[kg][half * 2 + 1] = pack_bf2(p2, p3);
                pl[kg][half * 2 + 0] = pack_bf2(p0 - h0, p1 - h1);
                pl[kg][half * 2 + 1] = pack_bf2(p2 - h2, p3 - h3);
            }
        }
        l0r = l0r * al0 + sum0;
        l1r = l1r * al1 + sum1;
        #pragma unroll
        for (int nb = 0; nb < 8; nb++) {
            o[nb][0] *= al0; o[nb][1] *= al0;
            o[nb][2] *= al1; o[nb][3] *= al1;
        }
        #pragma unroll
        for (int kg = 0; kg < 4; kg++) {
            #pragma unroll
            for (int ep = 0; ep < 4; ep++) {
                uint32_t vo = aoff(kg * 16 + (lane & 15), ep * 2 + khalf);
                uint32_t vbh[4], vbl[4];
                LDM4T(vbh, Vh + vo);
                LDM4T(vbl, Vl + vo);
                #pragma unroll
                for (int half = 0; half < 2; half++) {
                    float* d = o[ep * 2 + half];
                    MMA16816(d, ph[kg], vbh[half * 2], vbh[half * 2 + 1]);
                    MMA16816(d, ph[kg], vbl[half * 2], vbl[half * 2 + 1]);
                    MMA16816(d, pl[kg], vbh[half * 2], vbh[half * 2 + 1]);
                }
            }
        }
    }
    l0r += __shfl_xor_sync(0xffffffffu, l0r, 1);
    l0r += __shfl_xor_sync(0xffffffffu, l0r, 2);
    l1r += __shfl_xor_sync(0xffffffffu, l1r, 1);
    l1r += __shfl_xor_sync(0xffffffffu, l1r, 2);
    float inv0 = 1.f / l0r, inv1 = 1.f / l1r;
    int r0 = q0 + wid * 16 + g, r1 = r0 + 8;
    #pragma unroll
    for (int eb = 0; eb < 8; eb++) {
        int col = h * 64 + eb * 8 + t * 2;
        size_t o0 = (size_t)(b * SS + r0) * DD + col;
        size_t o1 = (size_t)(b * SS + r1) * DD + col;
        float v00 = o[eb][0] * inv0, v01 = o[eb][1] * inv0;
        float v10 = o[eb][2] * inv1, v11 = o[eb][3] * inv1;
        __nv_bfloat16 h0, l0, h1, l1, h2, l2, h3, l3;
        split_bf16(v00, h0, l0); split_bf16(v01, h1, l1);
        split_bf16(v10, h2, l2); split_bf16(v11, h3, l3);
        *(__nv_bfloat162*)(ohi + o0) = __halves2bfloat162(h0, h1);
        *(__nv_bfloat162*)(olo + o0) = __halves2bfloat162(l0, l1);
        *(__nv_bfloat162*)(ohi + o1) = __halves2bfloat162(h2, h3);
        *(__nv_bfloat162*)(olo + o1) = __halves2bfloat162(l2, l3);
    }
}

// ================= launch =================
extern "C" void kernel_launch(void* const* d_in, const int* in_sizes, int n_in,
                              void* d_out, int out_size)
{
    const float* x   = (const float*)d_in[0];
    const float* Wq  = (const float*)d_in[1];
    const float* bq  = (const float*)d_in[2];
    const float* Wk  = (const float*)d_in[3];
    const float* bk  = (const float*)d_in[4];
    const float* Wv  = (const float*)d_in[5];
    const float* bv  = (const float*)d_in[6];
    const float* Wo  = (const float*)d_in[7];
    const float* bo  = (const float*)d_in[8];
    const float* W1  = (const float*)d_in[9];
    const float* b1  = (const float*)d_in[10];
    const float* W2  = (const float*)d_in[11];
    const float* b2  = (const float*)d_in[12];
    const float* g1  = (const float*)d_in[13];
    const float* be1 = (const float*)d_in[14];
    const float* g2  = (const float*)d_in[15];
    const float* be2 = (const float*)d_in[16];
    float* out = (float*)d_out;

    void *ppart, *pbp, *phh, *phl, *pqh, *pql, *poh, *pol, *pfh, *pfl;
    void *pWoh, *pWol, *pW1h, *pW1l, *pW2h, *pW2l, *pWqh, *pWql;
    cudaGetSymbolAddress(&ppart, g_part);
    cudaGetSymbolAddress(&pbp,  g_bp);
    cudaGetSymbolAddress(&phh,  g_h_hi);  cudaGetSymbolAddress(&phl, g_h_lo);
    cudaGetSymbolAddress(&pqh,  g_qkvh);  cudaGetSymbolAddress(&pql, g_qkvl);
    cudaGetSymbolAddress(&poh,  g_o_hi);  cudaGetSymbolAddress(&pol, g_o_lo);
    cudaGetSymbolAddress(&pfh,  g_f_hi);  cudaGetSymbolAddress(&pfl, g_f_lo);
    cudaGetSymbolAddress(&pWqh, g_Wqkv_hi); cudaGetSymbolAddress(&pWql, g_Wqkv_lo);
    cudaGetSymbolAddress(&pWoh, g_Wo_hi);   cudaGetSymbolAddress(&pWol, g_Wo_lo);
    cudaGetSymbolAddress(&pW1h, g_W1_hi);   cudaGetSymbolAddress(&pW1l, g_W1_lo);
    cudaGetSymbolAddress(&pW2h, g_W2_hi);   cudaGetSymbolAddress(&pW2l, g_W2_lo);
    float* part = (float*)ppart;
    float* bp   = (float*)pbp;
    __nv_bfloat16* hh = (__nv_bfloat16*)phh, *hl = (__nv_bfloat16*)phl;
    __nv_bfloat16* qvh = (__nv_bfloat16*)pqh, *qvl = (__nv_bfloat16*)pql;
    __nv_bfloat16* oh = (__nv_bfloat16*)poh, *ol = (__nv_bfloat16*)pol;
    __nv_bfloat16* fh = (__nv_bfloat16*)pfh, *fl = (__nv_bfloat16*)pfl;
    __nv_bfloat16* Wqh = (__nv_bfloat16*)pWqh, *Wql = (__nv_bfloat16*)pWql;
    __nv_bfloat16* Woh = (__nv_bfloat16*)pWoh, *Wol = (__nv_bfloat16*)pWol;
    __nv_bfloat16* W1h = (__nv_bfloat16*)pW1h, *W1l = (__nv_bfloat16*)pW1l;
    __nv_bfloat16* W2h = (__nv_bfloat16*)pW2h, *W2l = (__nv_bfloat16*)pW2l;

    cudaFuncSetAttribute(tgemm<0,1,0>, cudaFuncAttributeMaxDynamicSharedMemorySize, GEMM_SMEM);
    cudaFuncSetAttribute(tgemm<0,0,1>, cudaFuncAttributeMaxDynamicSharedMemorySize, GEMM_SMEM);
    cudaFuncSetAttribute(tgemm<1,1,0>, cudaFuncAttributeMaxDynamicSharedMemorySize, GEMM_SMEM);
    cudaFuncSetAttribute(attn_tc,      cudaFuncAttributeMaxDynamicSharedMemorySize, ATT_SMEM);

    // weight prep (coalesced transposes)
    qkv_cvt_t<<<dim3(DD/32, HDD/32, 3*HH), dim3(32,8)>>>(Wq, Wk, Wv);
    qkv_bias<<<(NC + 255)/256, 256>>>(bq, bk, bv);
    tcvt_t<<<dim3(DD/32, DD/32),  dim3(32,8)>>>(Wo, Woh, Wol, DD, DD);
    tcvt_t<<<dim3(FF/32, DD/32),  dim3(32,8)>>>(W1, W1h, W1l, DD, FF);
    tcvt_t<<<dim3(DD/32, FF/32),  dim3(32,8)>>>(W2, W2h, W2l, FF, DD);
    // LN1 -> split
    ln_kernel<<<ROWS, 256>>>(x, g1, be1, hh, hl);
    // QKV projection -> split bf16 qkv
    tgemm<0,1,0><<<dim3(NC/128, ROWS/128), 256, GEMM_SMEM>>>(
        hh, hl, Wqh, Wql, bp, nullptr, qvh, qvl, NC, DD);
    // tensor-core flash attention -> split bf16 o
    attn_tc<<<dim3(SS/64, BB*HH), 128, ATT_SMEM>>>(qvh, qvl, oh, ol);
    // output projection: split-K=3 partials
    tgemm<0,0,1><<<dim3(DD/128, ROWS/128, 3), 256, GEMM_SMEM>>>(
        oh, ol, Woh, Wol, nullptr, part, nullptr, nullptr, DD, DD);
    // fused reduce + bias + LN2 -> split
    ln2_fuse<<<ROWS, 256>>>(bo, g2, be2, hh, hl);
    // FFN up + GELU -> split
    tgemm<1,1,0><<<dim3(FF/128, ROWS/128), 256, GEMM_SMEM>>>(
        hh, hl, W1h, W1l, b1, nullptr, fh, fl, FF, DD);
    // FFN down: split-K=3 partials
    tgemm<0,0,1><<<dim3(DD/128, ROWS/128, 3), 256, GEMM_SMEM>>>(
        fh, fl, W2h, W2l, nullptr, part, nullptr, nullptr, DD, FF);
    // reduce + bias -> output
    addbias3<<<(ROWS*DD/4 + 255)/256, 256>>>(b2, out);
}